// round 1
// baseline (speedup 1.0000x reference)
#include <cuda_runtime.h>
#include <cuda_bf16.h>
#include <cstdint>

// Fused: LayerNorm(x) @ W + b -> exact GELU -> + x (residual)
// Shapes: x [M, D] (M = B*S = 32768, D = 2048), W [D, H] (H = 2048), out [M, H]
//
// Kernel 1: per-row mean / rstd  -> __device__ scratch
// Kernel 2: tiled SIMT GEMM (BM=BN=128, BK=16, 256 thr, 8x8/thread) with
//           on-the-fly normalization of the A tile and fused epilogue.
//           Inner loop uses packed fma.rn.f32x2 (2 fp32 FMA lanes / instr).

#define LN_EPS 1e-5f

// scratch for row statistics (max 65536 rows; actual M = 32768)
__device__ float g_mu[65536];
__device__ float g_rstd[65536];

// ---------------------------------------------------------------------------
// packed f32x2 helpers
// ---------------------------------------------------------------------------
__device__ __forceinline__ unsigned long long pack2(float lo, float hi) {
    unsigned long long r;
    asm("mov.b64 %0, {%1, %2};" : "=l"(r) : "f"(lo), "f"(hi));
    return r;
}
__device__ __forceinline__ void unpack2(unsigned long long v, float& lo, float& hi) {
    asm("mov.b64 {%0, %1}, %2;" : "=f"(lo), "=f"(hi) : "l"(v));
}
#define FMA2(d, a, b, c) \
    asm("fma.rn.f32x2 %0, %1, %2, %3;" : "=l"(d) : "l"(a), "l"(b), "l"(c))

// ---------------------------------------------------------------------------
// Kernel 1: LayerNorm row statistics
// ---------------------------------------------------------------------------
__global__ void ln_stats_kernel(const float* __restrict__ x, int D) {
    const int row = blockIdx.x;
    const float* xr = x + (size_t)row * D;
    const int t = threadIdx.x;

    float s = 0.f, s2 = 0.f;
    for (int i = t * 4; i < D; i += blockDim.x * 4) {
        float4 v = *reinterpret_cast<const float4*>(xr + i);
        s  += v.x + v.y + v.z + v.w;
        s2 += v.x * v.x + v.y * v.y + v.z * v.z + v.w * v.w;
    }
    // warp reduce
    #pragma unroll
    for (int o = 16; o > 0; o >>= 1) {
        s  += __shfl_down_sync(0xFFFFFFFFu, s, o);
        s2 += __shfl_down_sync(0xFFFFFFFFu, s2, o);
    }
    __shared__ float ssum[8], ssum2[8];
    const int wid = t >> 5, lane = t & 31;
    if (lane == 0) { ssum[wid] = s; ssum2[wid] = s2; }
    __syncthreads();
    if (t == 0) {
        float S = 0.f, S2 = 0.f;
        #pragma unroll
        for (int i = 0; i < 8; i++) { S += ssum[i]; S2 += ssum2[i]; }
        float m   = S / (float)D;
        float var = S2 / (float)D - m * m;
        g_mu[row]   = m;
        g_rstd[row] = rsqrtf(var + LN_EPS);
    }
}

// ---------------------------------------------------------------------------
// Kernel 2: fused GEMM + bias + GELU + residual
// ---------------------------------------------------------------------------
__device__ __forceinline__ float gelu_exact(float h) {
    return 0.5f * h * (1.0f + erff(h * 0.70710678118654752f));
}

__global__ __launch_bounds__(256, 2)
void ffn_gemm_kernel(const float* __restrict__ x,
                     const float* __restrict__ gamma,
                     const float* __restrict__ beta,
                     const float* __restrict__ W,
                     const float* __restrict__ bias,
                     float* __restrict__ out,
                     int D, int H) {
    constexpr int BM = 128, BN = 128, BK = 16;

    __shared__ float As[BK][BM + 4];   // k-major, padded (16B-aligned rows)
    __shared__ float Bs[BK][BN];

    const int t  = threadIdx.x;
    const int m0 = blockIdx.y * BM;
    const int n0 = blockIdx.x * BN;

    const int rowBase = (t >> 4) * 8;  // 0..120
    const int colBase = (t & 15) * 8;  // 0..120

    unsigned long long acc[8][4];
    #pragma unroll
    for (int i = 0; i < 8; i++)
        #pragma unroll
        for (int j = 0; j < 4; j++) acc[i][j] = 0ull;

    for (int k0 = 0; k0 < D; k0 += BK) {
        // --- load + normalize A tile: As[k][m] = (x - mu)*rstd*gamma + beta
        #pragma unroll
        for (int li = 0; li < 2; li++) {
            const int idx = t + li * 256;      // 0..511
            const int row = idx >> 2;          // 0..127
            const int kq  = (idx & 3) * 4;     // 0,4,8,12
            float4 v  = *reinterpret_cast<const float4*>(x + (size_t)(m0 + row) * D + k0 + kq);
            float4 g  = *reinterpret_cast<const float4*>(gamma + k0 + kq);
            float4 be = *reinterpret_cast<const float4*>(beta  + k0 + kq);
            const float mu = g_mu[m0 + row];
            const float rs = g_rstd[m0 + row];
            As[kq + 0][row] = (v.x - mu) * rs * g.x + be.x;
            As[kq + 1][row] = (v.y - mu) * rs * g.y + be.y;
            As[kq + 2][row] = (v.z - mu) * rs * g.z + be.z;
            As[kq + 3][row] = (v.w - mu) * rs * g.w + be.w;
        }
        // --- load B tile: Bs[k][n]
        #pragma unroll
        for (int li = 0; li < 2; li++) {
            const int idx = t + li * 256;      // 0..511
            const int k   = idx >> 5;          // 0..15
            const int nq  = (idx & 31) * 4;    // 0..124
            *reinterpret_cast<float4*>(&Bs[k][nq]) =
                *reinterpret_cast<const float4*>(W + (size_t)(k0 + k) * H + n0 + nq);
        }
        __syncthreads();

        // --- compute
        #pragma unroll
        for (int kk = 0; kk < BK; kk++) {
            float4 a0 = *reinterpret_cast<const float4*>(&As[kk][rowBase]);
            float4 a1 = *reinterpret_cast<const float4*>(&As[kk][rowBase + 4]);
            const unsigned long long* Bp =
                reinterpret_cast<const unsigned long long*>(&Bs[kk][colBase]);
            unsigned long long b0 = Bp[0], b1 = Bp[1], b2 = Bp[2], b3 = Bp[3];

            float av[8] = {a0.x, a0.y, a0.z, a0.w, a1.x, a1.y, a1.z, a1.w};
            #pragma unroll
            for (int i = 0; i < 8; i++) {
                unsigned long long ad = pack2(av[i], av[i]);
                FMA2(acc[i][0], ad, b0, acc[i][0]);
                FMA2(acc[i][1], ad, b1, acc[i][1]);
                FMA2(acc[i][2], ad, b2, acc[i][2]);
                FMA2(acc[i][3], ad, b3, acc[i][3]);
            }
        }
        __syncthreads();
    }

    // --- epilogue: bias + exact GELU + residual (D == H here)
    #pragma unroll
    for (int i = 0; i < 8; i++) {
        const int m = m0 + rowBase + i;
        const float* xr = x + (size_t)m * D;
        float* orow = out + (size_t)m * H;
        #pragma unroll
        for (int j = 0; j < 4; j++) {
            const int n = n0 + colBase + j * 2;
            float c0, c1;
            unpack2(acc[i][j], c0, c1);
            float h0 = gelu_exact(c0 + bias[n])     + xr[n];
            float h1 = gelu_exact(c1 + bias[n + 1]) + xr[n + 1];
            orow[n]     = h0;
            orow[n + 1] = h1;
        }
    }
}

// ---------------------------------------------------------------------------
extern "C" void kernel_launch(void* const* d_in, const int* in_sizes, int n_in,
                              void* d_out, int out_size) {
    const float* x     = (const float*)d_in[0];
    const float* gamma = (const float*)d_in[1];
    const float* beta  = (const float*)d_in[2];
    const float* W     = (const float*)d_in[3];
    const float* bias  = (const float*)d_in[4];
    float* out = (float*)d_out;

    const int D = in_sizes[1];
    const int H = in_sizes[4];
    const int M = in_sizes[0] / D;

    ln_stats_kernel<<<M, 256>>>(x, D);

    dim3 grid(H / 128, M / 128);
    ffn_gemm_kernel<<<grid, 256>>>(x, gamma, beta, W, bias, out, D, H);
}

// round 4
// speedup vs baseline: 2.5859x; 2.5859x over previous
#include <cuda_runtime.h>
#include <cuda_bf16.h>
#include <cstdint>

// =====================================================================
// Fused LayerNorm -> Linear -> exact GELU -> residual
//   x [M=32768, D=2048] fp32, W [D, H=2048] fp32, out [M, H] fp32
// tcgen05 is sm_103a-gated and this harness compiles at compute_103 base,
// so the GEMM uses mma.sync.m16n8k16 bf16 (sm_80 base instruction) with a
// bf16 hi/lo split: D = Ahi*Bhi + Alo*Bhi + Ahi*Blo   (fp32 accumulate).
// Stage 1: LN + split normalized A -> g_Ahi/g_Alo  [M,K] K-major bf16
// Stage 2: W transpose+split       -> g_Bhi/g_Blo  [N,K] K-major bf16
// Stage 3: 128x256 CTA-tile GEMM, BK=32, 4-stage cp.async pipeline,
//          SW128-swizzled smem, fused bias+GELU+residual epilogue.
// =====================================================================

#define LN_EPS 1e-5f
static constexpr int MROWS = 32768;
static constexpr int DDIM  = 2048;

__device__ __align__(1024) __nv_bfloat16 g_Ahi[(size_t)MROWS * DDIM];
__device__ __align__(1024) __nv_bfloat16 g_Alo[(size_t)MROWS * DDIM];
__device__ __align__(1024) __nv_bfloat16 g_Bhi[(size_t)DDIM * DDIM];
__device__ __align__(1024) __nv_bfloat16 g_Blo[(size_t)DDIM * DDIM];

// ------------------------- helpers ----------------------------------
__device__ __forceinline__ uint32_t smem_u32(const void* p) {
    uint32_t a;
    asm("{ .reg .u64 t; cvta.to.shared.u64 t, %1; cvt.u32.u64 %0, t; }"
        : "=r"(a) : "l"(p));
    return a;
}
__device__ __forceinline__ uint32_t swz(uint32_t off) {   // SW128: bits[6:4] ^= bits[9:7]
    return off ^ ((off >> 3) & 0x70u);
}
__device__ __forceinline__ void cp16(uint32_t dst, const void* src) {
    asm volatile("cp.async.cg.shared.global [%0], [%1], 16;" :: "r"(dst), "l"(src));
}
__device__ __forceinline__ uint32_t lds32(uint32_t a) {
    uint32_t v;
    asm volatile("ld.shared.b32 %0, [%1];" : "=r"(v) : "r"(a));
    return v;
}
template <int IMM>
__device__ __forceinline__ uint32_t lds32o(uint32_t a) {
    uint32_t v;
    asm volatile("ld.shared.b32 %0, [%1+%2];" : "=r"(v) : "r"(a), "n"(IMM));
    return v;
}
__device__ __forceinline__ void mma16816(float* c, const uint32_t* a, const uint32_t* b) {
    asm volatile(
        "mma.sync.aligned.m16n8k16.row.col.f32.bf16.bf16.f32 "
        "{%0,%1,%2,%3}, {%4,%5,%6,%7}, {%8,%9}, {%0,%1,%2,%3};"
        : "+f"(c[0]), "+f"(c[1]), "+f"(c[2]), "+f"(c[3])
        : "r"(a[0]), "r"(a[1]), "r"(a[2]), "r"(a[3]), "r"(b[0]), "r"(b[1]));
}

// ------------------------- Stage 1: LN + split A --------------------
__global__ __launch_bounds__(256)
void ln_split_kernel(const float* __restrict__ x,
                     const float* __restrict__ gamma,
                     const float* __restrict__ beta, int D) {
    const int row = blockIdx.x;
    const int t = threadIdx.x;
    const float* xr = x + (size_t)row * D;

    float4 v0 = *reinterpret_cast<const float4*>(xr + t * 8);
    float4 v1 = *reinterpret_cast<const float4*>(xr + t * 8 + 4);

    float s  = v0.x + v0.y + v0.z + v0.w + v1.x + v1.y + v1.z + v1.w;
    float s2 = v0.x*v0.x + v0.y*v0.y + v0.z*v0.z + v0.w*v0.w
             + v1.x*v1.x + v1.y*v1.y + v1.z*v1.z + v1.w*v1.w;
    #pragma unroll
    for (int o = 16; o > 0; o >>= 1) {
        s  += __shfl_down_sync(0xFFFFFFFFu, s, o);
        s2 += __shfl_down_sync(0xFFFFFFFFu, s2, o);
    }
    __shared__ float ps[8], ps2[8], s_mu, s_rs;
    const int wid = t >> 5, lane = t & 31;
    if (lane == 0) { ps[wid] = s; ps2[wid] = s2; }
    __syncthreads();
    if (t == 0) {
        float S = 0.f, S2 = 0.f;
        #pragma unroll
        for (int i = 0; i < 8; i++) { S += ps[i]; S2 += ps2[i]; }
        float m = S / (float)D;
        s_mu = m;
        s_rs = rsqrtf(S2 / (float)D - m * m + LN_EPS);
    }
    __syncthreads();
    const float mu = s_mu, rs = s_rs;

    float4 g0 = *reinterpret_cast<const float4*>(gamma + t * 8);
    float4 g1 = *reinterpret_cast<const float4*>(gamma + t * 8 + 4);
    float4 b0 = *reinterpret_cast<const float4*>(beta  + t * 8);
    float4 b1 = *reinterpret_cast<const float4*>(beta  + t * 8 + 4);

    float xn[8] = {
        (v0.x - mu) * rs * g0.x + b0.x, (v0.y - mu) * rs * g0.y + b0.y,
        (v0.z - mu) * rs * g0.z + b0.z, (v0.w - mu) * rs * g0.w + b0.w,
        (v1.x - mu) * rs * g1.x + b1.x, (v1.y - mu) * rs * g1.y + b1.y,
        (v1.z - mu) * rs * g1.z + b1.z, (v1.w - mu) * rs * g1.w + b1.w };

    union { __nv_bfloat16 h[8]; uint4 u; } H, L;
    #pragma unroll
    for (int i = 0; i < 8; i++) {
        __nv_bfloat16 hi = __float2bfloat16(xn[i]);
        H.h[i] = hi;
        L.h[i] = __float2bfloat16(xn[i] - __bfloat162float(hi));
    }
    const size_t o = (size_t)row * D + t * 8;
    *reinterpret_cast<uint4*>(&g_Ahi[o]) = H.u;
    *reinterpret_cast<uint4*>(&g_Alo[o]) = L.u;
}

// ------------------------- Stage 2: W transpose + split -------------
__global__ __launch_bounds__(256)
void wsplit_kernel(const float* __restrict__ W, int K, int N) {
    __shared__ float tile[32][33];
    const int k0 = blockIdx.y * 32, n0 = blockIdx.x * 32;
    const int tx = threadIdx.x, ty = threadIdx.y;  // 32 x 8
    #pragma unroll
    for (int r = 0; r < 32; r += 8)
        tile[ty + r][tx] = W[(size_t)(k0 + ty + r) * N + n0 + tx];
    __syncthreads();
    #pragma unroll
    for (int r = 0; r < 32; r += 8) {
        const int n = n0 + ty + r, k = k0 + tx;
        float v = tile[tx][ty + r];
        __nv_bfloat16 hi = __float2bfloat16(v);
        g_Bhi[(size_t)n * K + k] = hi;
        g_Blo[(size_t)n * K + k] = __float2bfloat16(v - __bfloat162float(hi));
    }
}

// ------------------------- Stage 3: GEMM ----------------------------
static constexpr int BM = 128, BN = 256, BK = 32;
static constexpr int STAGES = 4;
// per-stage layout (bytes, swizzle-transparent 1024-multiples):
//   Ahi [0,8192)  Alo [8192,16384)  Bhi [16384,32768)  Blo [32768,49152)
static constexpr int A_LO_OFF  = 8192;
static constexpr int B_OFF     = 16384;
static constexpr int B_LO_OFF  = 16384;   // relative to Bhi
static constexpr int STAGE_BYTES = 49152;
static constexpr int SMEM_TOTAL  = 1024 + STAGES * STAGE_BYTES;  // 197632

__global__ __launch_bounds__(256, 1)
void ffn_mma_kernel(const float* __restrict__ x,
                    const float* __restrict__ bias,
                    float* __restrict__ out,
                    int K, int H) {
    extern __shared__ __align__(1024) uint8_t dynsmem[];
    uint32_t sb = smem_u32(dynsmem);
    sb = (sb + 1023) & ~1023u;

    const int t    = threadIdx.x;
    const int lane = t & 31;
    const int wid  = t >> 5;
    const int g    = lane >> 2;   // group id 0..7
    const int tg   = lane & 3;    // thread-in-group
    const int m0   = blockIdx.y * BM;
    const int n0   = blockIdx.x * BN;
    const int wm   = (wid >> 2) * 64;   // warp m offset within CTA tile
    const int wn   = (wid & 3)  * 64;   // warp n offset

    // ---- cp.async source pointers (per thread) ----
    const size_t aoff = (size_t)(m0 + (t >> 2)) * K + (t & 3) * 8;
    const size_t boff = (size_t)(n0 + (t >> 2)) * K + (t & 3) * 8;
    const __nv_bfloat16* pAhi = g_Ahi + aoff;
    const __nv_bfloat16* pAlo = g_Alo + aoff;
    const __nv_bfloat16* pBhi = g_Bhi + boff;
    const __nv_bfloat16* pBlo = g_Blo + boff;
    const size_t rstep = (size_t)64 * K;   // +64 rows

    // ---- cp.async dst (stage 0, swizzled; +4096 per 64-row block is transparent)
    const uint32_t dstA = sb + swz((uint32_t)((t >> 2) * 64 + (t & 3) * 16));
    const uint32_t dstB = sb + B_OFF + swz((uint32_t)((t >> 2) * 64 + (t & 3) * 16));

    // ---- fragment LDS addresses (stage 0, hi buffers, ks=0) ----
    uint32_t aAdr[4][2], bAdr[8];
    #pragma unroll
    for (int mt = 0; mt < 4; mt++) {
        const uint32_t r = wm + mt * 16 + g;
        aAdr[mt][0] = sb + swz(r * 64 + tg * 4);
        aAdr[mt][1] = sb + swz((r + 8) * 64 + tg * 4);
    }
    #pragma unroll
    for (int nt = 0; nt < 8; nt++) {
        const uint32_t r = wn + nt * 8 + g;
        bAdr[nt] = sb + B_OFF + swz(r * 64 + tg * 4);
    }

    float acc[4][8][4];
    #pragma unroll
    for (int mt = 0; mt < 4; mt++)
        #pragma unroll
        for (int nt = 0; nt < 8; nt++)
            #pragma unroll
            for (int r = 0; r < 4; r++) acc[mt][nt][r] = 0.f;

    const int NT = K / BK;   // 64

    // ---- pipeline prologue: stages 0..2 ----
    #pragma unroll
    for (int s = 0; s < STAGES - 1; s++) {
        const uint32_t so = s * STAGE_BYTES;
        const __nv_bfloat16* ah = pAhi + s * 32;
        const __nv_bfloat16* al = pAlo + s * 32;
        const __nv_bfloat16* bh = pBhi + s * 32;
        const __nv_bfloat16* bl = pBlo + s * 32;
        cp16(dstA + so,                    ah);
        cp16(dstA + so + 4096,             ah + rstep);
        cp16(dstA + so + A_LO_OFF,         al);
        cp16(dstA + so + A_LO_OFF + 4096,  al + rstep);
        #pragma unroll
        for (int i = 0; i < 4; i++) {
            cp16(dstB + so + i * 4096,            bh + i * rstep);
            cp16(dstB + so + B_LO_OFF + i * 4096, bl + i * rstep);
        }
        asm volatile("cp.async.commit_group;" ::: "memory");
    }

    // ---- main loop ----
    for (int kt = 0; kt < NT; kt++) {
        asm volatile("cp.async.wait_group 2;" ::: "memory");
        __syncthreads();

        if (kt + STAGES - 1 < NT) {
            const int s = kt + STAGES - 1;
            const uint32_t so = (s & 3) * STAGE_BYTES;
            const __nv_bfloat16* ah = pAhi + s * 32;
            const __nv_bfloat16* al = pAlo + s * 32;
            const __nv_bfloat16* bh = pBhi + s * 32;
            const __nv_bfloat16* bl = pBlo + s * 32;
            cp16(dstA + so,                    ah);
            cp16(dstA + so + 4096,             ah + rstep);
            cp16(dstA + so + A_LO_OFF,         al);
            cp16(dstA + so + A_LO_OFF + 4096,  al + rstep);
            #pragma unroll
            for (int i = 0; i < 4; i++) {
                cp16(dstB + so + i * 4096,            bh + i * rstep);
                cp16(dstB + so + B_LO_OFF + i * 4096, bl + i * rstep);
            }
        }
        asm volatile("cp.async.commit_group;" ::: "memory");

        const uint32_t so = (kt & 3) * STAGE_BYTES;

        #pragma unroll
        for (int ks = 0; ks < 2; ks++) {
            const uint32_t kx = ks * 32;   // swizzle-linear bit5 toggle
            uint32_t bh[16], bl[16];
            #pragma unroll
            for (int nt = 0; nt < 8; nt++) {
                const uint32_t a0 = (bAdr[nt] + so) ^ kx;
                bh[nt*2]   = lds32(a0);
                bh[nt*2+1] = lds32(a0 ^ 16u);
                bl[nt*2]   = lds32o<B_LO_OFF>(a0);
                bl[nt*2+1] = lds32o<B_LO_OFF>(a0 ^ 16u);
            }
            #pragma unroll
            for (int mt = 0; mt < 4; mt++) {
                const uint32_t a0 = (aAdr[mt][0] + so) ^ kx;
                const uint32_t a1 = (aAdr[mt][1] + so) ^ kx;
                uint32_t ah[4], al[4];
                ah[0] = lds32(a0);          ah[1] = lds32(a1);
                ah[2] = lds32(a0 ^ 16u);    ah[3] = lds32(a1 ^ 16u);
                al[0] = lds32o<A_LO_OFF>(a0);        al[1] = lds32o<A_LO_OFF>(a1);
                al[2] = lds32o<A_LO_OFF>(a0 ^ 16u);  al[3] = lds32o<A_LO_OFF>(a1 ^ 16u);
                #pragma unroll
                for (int nt = 0; nt < 8; nt++) {
                    mma16816(acc[mt][nt], ah, &bh[nt*2]);   // hi*hi
                    mma16816(acc[mt][nt], al, &bh[nt*2]);   // lo*hi
                    mma16816(acc[mt][nt], ah, &bl[nt*2]);   // hi*lo
                }
            }
        }
    }

    // ---- epilogue: bias + exact GELU + residual ----
    #pragma unroll
    for (int mt = 0; mt < 4; mt++) {
        #pragma unroll
        for (int half = 0; half < 2; half++) {
            const int m = m0 + wm + mt * 16 + g + half * 8;
            const float* xr = x + (size_t)m * H;
            float* orow = out + (size_t)m * H;
            #pragma unroll
            for (int nt = 0; nt < 8; nt++) {
                const int n = n0 + wn + nt * 8 + tg * 2;
                float c0 = acc[mt][nt][half * 2 + 0];
                float c1 = acc[mt][nt][half * 2 + 1];
                const float2 bb = *reinterpret_cast<const float2*>(bias + n);
                float h0 = c0 + bb.x, h1 = c1 + bb.y;
                h0 = 0.5f * h0 * (1.0f + erff(h0 * 0.70710678118654752f));
                h1 = 0.5f * h1 * (1.0f + erff(h1 * 0.70710678118654752f));
                const float2 xv = *reinterpret_cast<const float2*>(xr + n);
                float2 o;
                o.x = h0 + xv.x;
                o.y = h1 + xv.y;
                *reinterpret_cast<float2*>(orow + n) = o;
            }
        }
    }
}

// ------------------------- host side ---------------------------------
extern "C" void kernel_launch(void* const* d_in, const int* in_sizes, int n_in,
                              void* d_out, int out_size) {
    const float* x     = (const float*)d_in[0];
    const float* gamma = (const float*)d_in[1];
    const float* beta  = (const float*)d_in[2];
    const float* W     = (const float*)d_in[3];
    const float* bias  = (const float*)d_in[4];
    float* out = (float*)d_out;

    const int D = in_sizes[1];
    const int H = in_sizes[4];
    const int M = in_sizes[0] / D;

    ln_split_kernel<<<M, 256>>>(x, gamma, beta, D);

    dim3 wgrid(H / 32, D / 32);
    wsplit_kernel<<<wgrid, dim3(32, 8)>>>(W, D, H);

    cudaFuncSetAttribute(ffn_mma_kernel,
                         cudaFuncAttributeMaxDynamicSharedMemorySize, SMEM_TOTAL);
    dim3 ggrid(H / BN, M / BM);
    ffn_mma_kernel<<<ggrid, 256, SMEM_TOTAL>>>(x, bias, out, D, H);
}

// round 5
// speedup vs baseline: 2.7153x; 1.0501x over previous
#include <cuda_runtime.h>
#include <cuda_bf16.h>
#include <cstdint>

// =====================================================================
// Fused LayerNorm -> Linear -> exact GELU -> residual
//   x [M=32768, D=2048] fp32, W [D, H=2048] fp32, out [M, H] fp32
// GEMM via mma.sync.m16n8k16 bf16 with hi/lo split:
//   D = Ahi*Bhi + Alo*Bhi + Ahi*Blo   (fp32 accumulate)
// R5: fragment loads via ldmatrix.m8n8.x4 (128 LDS.32 -> 32 LDSM per kt).
// =====================================================================

#define LN_EPS 1e-5f
static constexpr int MROWS = 32768;
static constexpr int DDIM  = 2048;

__device__ __align__(1024) __nv_bfloat16 g_Ahi[(size_t)MROWS * DDIM];
__device__ __align__(1024) __nv_bfloat16 g_Alo[(size_t)MROWS * DDIM];
__device__ __align__(1024) __nv_bfloat16 g_Bhi[(size_t)DDIM * DDIM];
__device__ __align__(1024) __nv_bfloat16 g_Blo[(size_t)DDIM * DDIM];

// ------------------------- helpers ----------------------------------
__device__ __forceinline__ uint32_t smem_u32(const void* p) {
    uint32_t a;
    asm("{ .reg .u64 t; cvta.to.shared.u64 t, %1; cvt.u32.u64 %0, t; }"
        : "=r"(a) : "l"(p));
    return a;
}
__device__ __forceinline__ uint32_t swz(uint32_t off) {   // SW128: bits[6:4] ^= bits[9:7]
    return off ^ ((off >> 3) & 0x70u);
}
__device__ __forceinline__ void cp16(uint32_t dst, const void* src) {
    asm volatile("cp.async.cg.shared.global [%0], [%1], 16;" :: "r"(dst), "l"(src));
}
__device__ __forceinline__ void ldsm4(uint32_t* r, uint32_t a) {
    asm volatile("ldmatrix.sync.aligned.m8n8.x4.shared.b16 {%0,%1,%2,%3}, [%4];"
        : "=r"(r[0]), "=r"(r[1]), "=r"(r[2]), "=r"(r[3]) : "r"(a));
}
template <int IMM>
__device__ __forceinline__ void ldsm4o(uint32_t* r, uint32_t a) {
    asm volatile("ldmatrix.sync.aligned.m8n8.x4.shared.b16 {%0,%1,%2,%3}, [%4+%5];"
        : "=r"(r[0]), "=r"(r[1]), "=r"(r[2]), "=r"(r[3]) : "r"(a), "n"(IMM));
}
__device__ __forceinline__ void mma16816(float* c, const uint32_t* a, const uint32_t* b) {
    asm volatile(
        "mma.sync.aligned.m16n8k16.row.col.f32.bf16.bf16.f32 "
        "{%0,%1,%2,%3}, {%4,%5,%6,%7}, {%8,%9}, {%0,%1,%2,%3};"
        : "+f"(c[0]), "+f"(c[1]), "+f"(c[2]), "+f"(c[3])
        : "r"(a[0]), "r"(a[1]), "r"(a[2]), "r"(a[3]), "r"(b[0]), "r"(b[1]));
}

// ------------------------- Stage 1: LN + split A --------------------
__global__ __launch_bounds__(256)
void ln_split_kernel(const float* __restrict__ x,
                     const float* __restrict__ gamma,
                     const float* __restrict__ beta, int D) {
    const int row = blockIdx.x;
    const int t = threadIdx.x;
    const float* xr = x + (size_t)row * D;

    float4 v0 = *reinterpret_cast<const float4*>(xr + t * 8);
    float4 v1 = *reinterpret_cast<const float4*>(xr + t * 8 + 4);

    float s  = v0.x + v0.y + v0.z + v0.w + v1.x + v1.y + v1.z + v1.w;
    float s2 = v0.x*v0.x + v0.y*v0.y + v0.z*v0.z + v0.w*v0.w
             + v1.x*v1.x + v1.y*v1.y + v1.z*v1.z + v1.w*v1.w;
    #pragma unroll
    for (int o = 16; o > 0; o >>= 1) {
        s  += __shfl_down_sync(0xFFFFFFFFu, s, o);
        s2 += __shfl_down_sync(0xFFFFFFFFu, s2, o);
    }
    __shared__ float ps[8], ps2[8], s_mu, s_rs;
    const int wid = t >> 5, lane = t & 31;
    if (lane == 0) { ps[wid] = s; ps2[wid] = s2; }
    __syncthreads();
    if (t == 0) {
        float S = 0.f, S2 = 0.f;
        #pragma unroll
        for (int i = 0; i < 8; i++) { S += ps[i]; S2 += ps2[i]; }
        float m = S / (float)D;
        s_mu = m;
        s_rs = rsqrtf(S2 / (float)D - m * m + LN_EPS);
    }
    __syncthreads();
    const float mu = s_mu, rs = s_rs;

    float4 g0 = *reinterpret_cast<const float4*>(gamma + t * 8);
    float4 g1 = *reinterpret_cast<const float4*>(gamma + t * 8 + 4);
    float4 b0 = *reinterpret_cast<const float4*>(beta  + t * 8);
    float4 b1 = *reinterpret_cast<const float4*>(beta  + t * 8 + 4);

    float xn[8] = {
        (v0.x - mu) * rs * g0.x + b0.x, (v0.y - mu) * rs * g0.y + b0.y,
        (v0.z - mu) * rs * g0.z + b0.z, (v0.w - mu) * rs * g0.w + b0.w,
        (v1.x - mu) * rs * g1.x + b1.x, (v1.y - mu) * rs * g1.y + b1.y,
        (v1.z - mu) * rs * g1.z + b1.z, (v1.w - mu) * rs * g1.w + b1.w };

    union { __nv_bfloat16 h[8]; uint4 u; } H, L;
    #pragma unroll
    for (int i = 0; i < 8; i++) {
        __nv_bfloat16 hi = __float2bfloat16(xn[i]);
        H.h[i] = hi;
        L.h[i] = __float2bfloat16(xn[i] - __bfloat162float(hi));
    }
    const size_t o = (size_t)row * D + t * 8;
    *reinterpret_cast<uint4*>(&g_Ahi[o]) = H.u;
    *reinterpret_cast<uint4*>(&g_Alo[o]) = L.u;
}

// ------------------------- Stage 2: W transpose + split -------------
__global__ __launch_bounds__(256)
void wsplit_kernel(const float* __restrict__ W, int K, int N) {
    __shared__ float tile[32][33];
    const int k0 = blockIdx.y * 32, n0 = blockIdx.x * 32;
    const int tx = threadIdx.x, ty = threadIdx.y;  // 32 x 8
    #pragma unroll
    for (int r = 0; r < 32; r += 8)
        tile[ty + r][tx] = W[(size_t)(k0 + ty + r) * N + n0 + tx];
    __syncthreads();
    #pragma unroll
    for (int r = 0; r < 32; r += 8) {
        const int n = n0 + ty + r, k = k0 + tx;
        float v = tile[tx][ty + r];
        __nv_bfloat16 hi = __float2bfloat16(v);
        g_Bhi[(size_t)n * K + k] = hi;
        g_Blo[(size_t)n * K + k] = __float2bfloat16(v - __bfloat162float(hi));
    }
}

// ------------------------- Stage 3: GEMM ----------------------------
static constexpr int BM = 128, BN = 256, BK = 32;
static constexpr int STAGES = 4;
// per-stage layout: Ahi [0,8192) Alo [8192,16384) Bhi [16384,32768) Blo [32768,49152)
static constexpr int A_LO_OFF  = 8192;
static constexpr int B_OFF     = 16384;
static constexpr int B_LO_OFF  = 16384;   // relative to Bhi
static constexpr int STAGE_BYTES = 49152;
static constexpr int SMEM_TOTAL  = 1024 + STAGES * STAGE_BYTES;  // 197632

__global__ __launch_bounds__(256, 1)
void ffn_mma_kernel(const float* __restrict__ x,
                    const float* __restrict__ bias,
                    float* __restrict__ out,
                    int K, int H) {
    extern __shared__ __align__(1024) uint8_t dynsmem[];
    uint32_t sb = smem_u32(dynsmem);
    sb = (sb + 1023) & ~1023u;

    const int t    = threadIdx.x;
    const int lane = t & 31;
    const int wid  = t >> 5;
    const int g    = lane >> 2;
    const int tg   = lane & 3;
    const int m0   = blockIdx.y * BM;
    const int n0   = blockIdx.x * BN;
    const int wm   = (wid >> 2) * 64;
    const int wn   = (wid & 3)  * 64;

    // ---- cp.async source pointers ----
    const size_t aoff = (size_t)(m0 + (t >> 2)) * K + (t & 3) * 8;
    const size_t boff = (size_t)(n0 + (t >> 2)) * K + (t & 3) * 8;
    const __nv_bfloat16* pAhi = g_Ahi + aoff;
    const __nv_bfloat16* pAlo = g_Alo + aoff;
    const __nv_bfloat16* pBhi = g_Bhi + boff;
    const __nv_bfloat16* pBlo = g_Blo + boff;
    const size_t rstep = (size_t)64 * K;

    const uint32_t dstA = sb + swz((uint32_t)((t >> 2) * 64 + (t & 3) * 16));
    const uint32_t dstB = sb + B_OFF + swz((uint32_t)((t >> 2) * 64 + (t & 3) * 16));

    // ---- ldmatrix base addresses (stage 0, ks=0, hi buffers) ----
    // A, per mt: x4 mats [mlo,klo][mhi,klo][mlo,khi][mhi,khi]
    //   lane l: mat=l>>3, r8=l&7 -> m = wm+mt*16+(mat&1)*8+r8, kb=(mat>>1)*16
    const int matid = lane >> 3, r8 = lane & 7;
    uint32_t aAdr[4], bAdr[4];
    #pragma unroll
    for (int mt = 0; mt < 4; mt++) {
        const uint32_t m = wm + mt * 16 + (matid & 1) * 8 + r8;
        aAdr[mt] = sb + swz(m * 64 + (matid >> 1) * 16);
    }
    // B, per nt-pair p (nt=2p,2p+1): mats [nt,klo][nt,khi][nt+1,klo][nt+1,khi]
    //   lane l: n = wn+p*16+(mat>>1)*8+r8, kb=(mat&1)*16
    #pragma unroll
    for (int p = 0; p < 4; p++) {
        const uint32_t n = wn + p * 16 + (matid >> 1) * 8 + r8;
        bAdr[p] = sb + B_OFF + swz(n * 64 + (matid & 1) * 16);
    }

    float acc[4][8][4];
    #pragma unroll
    for (int mt = 0; mt < 4; mt++)
        #pragma unroll
        for (int nt = 0; nt < 8; nt++)
            #pragma unroll
            for (int r = 0; r < 4; r++) acc[mt][nt][r] = 0.f;

    const int NT = K / BK;   // 64

    // ---- pipeline prologue ----
    #pragma unroll
    for (int s = 0; s < STAGES - 1; s++) {
        const uint32_t so = s * STAGE_BYTES;
        const __nv_bfloat16* ah = pAhi + s * 32;
        const __nv_bfloat16* al = pAlo + s * 32;
        const __nv_bfloat16* bh = pBhi + s * 32;
        const __nv_bfloat16* bl = pBlo + s * 32;
        cp16(dstA + so,                    ah);
        cp16(dstA + so + 4096,             ah + rstep);
        cp16(dstA + so + A_LO_OFF,         al);
        cp16(dstA + so + A_LO_OFF + 4096,  al + rstep);
        #pragma unroll
        for (int i = 0; i < 4; i++) {
            cp16(dstB + so + i * 4096,            bh + i * rstep);
            cp16(dstB + so + B_LO_OFF + i * 4096, bl + i * rstep);
        }
        asm volatile("cp.async.commit_group;" ::: "memory");
    }

    // ---- main loop ----
    for (int kt = 0; kt < NT; kt++) {
        asm volatile("cp.async.wait_group 2;" ::: "memory");
        __syncthreads();

        if (kt + STAGES - 1 < NT) {
            const int s = kt + STAGES - 1;
            const uint32_t so = (s & 3) * STAGE_BYTES;
            const __nv_bfloat16* ah = pAhi + s * 32;
            const __nv_bfloat16* al = pAlo + s * 32;
            const __nv_bfloat16* bh = pBhi + s * 32;
            const __nv_bfloat16* bl = pBlo + s * 32;
            cp16(dstA + so,                    ah);
            cp16(dstA + so + 4096,             ah + rstep);
            cp16(dstA + so + A_LO_OFF,         al);
            cp16(dstA + so + A_LO_OFF + 4096,  al + rstep);
            #pragma unroll
            for (int i = 0; i < 4; i++) {
                cp16(dstB + so + i * 4096,            bh + i * rstep);
                cp16(dstB + so + B_LO_OFF + i * 4096, bl + i * rstep);
            }
        }
        asm volatile("cp.async.commit_group;" ::: "memory");

        const uint32_t so = (kt & 3) * STAGE_BYTES;

        #pragma unroll
        for (int ks = 0; ks < 2; ks++) {
            const uint32_t kx = ks * 32;   // bit-5 toggle, swizzle-transparent
            uint32_t bh[16], bl[16];
            #pragma unroll
            for (int p = 0; p < 4; p++) {
                const uint32_t a = (bAdr[p] + so) ^ kx;
                ldsm4(&bh[p * 4], a);
                ldsm4o<B_LO_OFF>(&bl[p * 4], a);
            }
            #pragma unroll
            for (int mt = 0; mt < 4; mt++) {
                const uint32_t a = (aAdr[mt] + so) ^ kx;
                uint32_t ah[4], al[4];
                ldsm4(ah, a);
                ldsm4o<A_LO_OFF>(al, a);
                #pragma unroll
                for (int nt = 0; nt < 8; nt++) {
                    mma16816(acc[mt][nt], ah, &bh[nt * 2]);   // hi*hi
                    mma16816(acc[mt][nt], al, &bh[nt * 2]);   // lo*hi
                    mma16816(acc[mt][nt], ah, &bl[nt * 2]);   // hi*lo
                }
            }
        }
    }

    // ---- epilogue: bias + exact GELU + residual ----
    #pragma unroll
    for (int mt = 0; mt < 4; mt++) {
        #pragma unroll
        for (int half = 0; half < 2; half++) {
            const int m = m0 + wm + mt * 16 + g + half * 8;
            const float* xr = x + (size_t)m * H;
            float* orow = out + (size_t)m * H;
            #pragma unroll
            for (int nt = 0; nt < 8; nt++) {
                const int n = n0 + wn + nt * 8 + tg * 2;
                float c0 = acc[mt][nt][half * 2 + 0];
                float c1 = acc[mt][nt][half * 2 + 1];
                const float2 bb = *reinterpret_cast<const float2*>(bias + n);
                float h0 = c0 + bb.x, h1 = c1 + bb.y;
                h0 = 0.5f * h0 * (1.0f + erff(h0 * 0.70710678118654752f));
                h1 = 0.5f * h1 * (1.0f + erff(h1 * 0.70710678118654752f));
                const float2 xv = *reinterpret_cast<const float2*>(xr + n);
                float2 o;
                o.x = h0 + xv.x;
                o.y = h1 + xv.y;
                *reinterpret_cast<float2*>(orow + n) = o;
            }
        }
    }
}

// ------------------------- host side ---------------------------------
extern "C" void kernel_launch(void* const* d_in, const int* in_sizes, int n_in,
                              void* d_out, int out_size) {
    const float* x     = (const float*)d_in[0];
    const float* gamma = (const float*)d_in[1];
    const float* beta  = (const float*)d_in[2];
    const float* W     = (const float*)d_in[3];
    const float* bias  = (const float*)d_in[4];
    float* out = (float*)d_out;

    const int D = in_sizes[1];
    const int H = in_sizes[4];
    const int M = in_sizes[0] / D;

    ln_split_kernel<<<M, 256>>>(x, gamma, beta, D);

    dim3 wgrid(H / 32, D / 32);
    wsplit_kernel<<<wgrid, dim3(32, 8)>>>(W, D, H);

    cudaFuncSetAttribute(ffn_mma_kernel,
                         cudaFuncAttributeMaxDynamicSharedMemorySize, SMEM_TOTAL);
    dim3 ggrid(H / BN, M / BM);
    ffn_mma_kernel<<<ggrid, 256, SMEM_TOTAL>>>(x, bias, out, D, H);
}

// round 6
// speedup vs baseline: 2.8054x; 1.0332x over previous
#include <cuda_runtime.h>
#include <cuda_bf16.h>
#include <cstdint>

// =====================================================================
// Fused LayerNorm -> Linear -> exact GELU -> residual
//   x [M=32768, D=2048] fp32, W [D, H=2048] fp32, out [M, H] fp32
// GEMM via mma.sync.m16n8k16 bf16 with hi/lo split:
//   D = Ahi*Bhi + Alo*Bhi + Ahi*Blo   (fp32 accumulate)
// R6: 512 threads (16 warps, 4/SMSP), warp tile 64x32, product-outer
//     MMA ordering to break accumulator RAW chains.
// =====================================================================

#define LN_EPS 1e-5f
static constexpr int MROWS = 32768;
static constexpr int DDIM  = 2048;

__device__ __align__(1024) __nv_bfloat16 g_Ahi[(size_t)MROWS * DDIM];
__device__ __align__(1024) __nv_bfloat16 g_Alo[(size_t)MROWS * DDIM];
__device__ __align__(1024) __nv_bfloat16 g_Bhi[(size_t)DDIM * DDIM];
__device__ __align__(1024) __nv_bfloat16 g_Blo[(size_t)DDIM * DDIM];

// ------------------------- helpers ----------------------------------
__device__ __forceinline__ uint32_t smem_u32(const void* p) {
    uint32_t a;
    asm("{ .reg .u64 t; cvta.to.shared.u64 t, %1; cvt.u32.u64 %0, t; }"
        : "=r"(a) : "l"(p));
    return a;
}
__device__ __forceinline__ uint32_t swz(uint32_t off) {   // SW128: bits[6:4] ^= bits[9:7]
    return off ^ ((off >> 3) & 0x70u);
}
__device__ __forceinline__ void cp16(uint32_t dst, const void* src) {
    asm volatile("cp.async.cg.shared.global [%0], [%1], 16;" :: "r"(dst), "l"(src));
}
__device__ __forceinline__ void ldsm4(uint32_t* r, uint32_t a) {
    asm volatile("ldmatrix.sync.aligned.m8n8.x4.shared.b16 {%0,%1,%2,%3}, [%4];"
        : "=r"(r[0]), "=r"(r[1]), "=r"(r[2]), "=r"(r[3]) : "r"(a));
}
template <int IMM>
__device__ __forceinline__ void ldsm4o(uint32_t* r, uint32_t a) {
    asm volatile("ldmatrix.sync.aligned.m8n8.x4.shared.b16 {%0,%1,%2,%3}, [%4+%5];"
        : "=r"(r[0]), "=r"(r[1]), "=r"(r[2]), "=r"(r[3]) : "r"(a), "n"(IMM));
}
__device__ __forceinline__ void mma16816(float* c, const uint32_t* a, const uint32_t* b) {
    asm volatile(
        "mma.sync.aligned.m16n8k16.row.col.f32.bf16.bf16.f32 "
        "{%0,%1,%2,%3}, {%4,%5,%6,%7}, {%8,%9}, {%0,%1,%2,%3};"
        : "+f"(c[0]), "+f"(c[1]), "+f"(c[2]), "+f"(c[3])
        : "r"(a[0]), "r"(a[1]), "r"(a[2]), "r"(a[3]), "r"(b[0]), "r"(b[1]));
}

// ------------------------- Stage 1: LN + split A --------------------
__global__ __launch_bounds__(256)
void ln_split_kernel(const float* __restrict__ x,
                     const float* __restrict__ gamma,
                     const float* __restrict__ beta, int D) {
    const int row = blockIdx.x;
    const int t = threadIdx.x;
    const float* xr = x + (size_t)row * D;

    float4 v0 = *reinterpret_cast<const float4*>(xr + t * 8);
    float4 v1 = *reinterpret_cast<const float4*>(xr + t * 8 + 4);

    float s  = v0.x + v0.y + v0.z + v0.w + v1.x + v1.y + v1.z + v1.w;
    float s2 = v0.x*v0.x + v0.y*v0.y + v0.z*v0.z + v0.w*v0.w
             + v1.x*v1.x + v1.y*v1.y + v1.z*v1.z + v1.w*v1.w;
    #pragma unroll
    for (int o = 16; o > 0; o >>= 1) {
        s  += __shfl_down_sync(0xFFFFFFFFu, s, o);
        s2 += __shfl_down_sync(0xFFFFFFFFu, s2, o);
    }
    __shared__ float ps[8], ps2[8], s_mu, s_rs;
    const int wid = t >> 5, lane = t & 31;
    if (lane == 0) { ps[wid] = s; ps2[wid] = s2; }
    __syncthreads();
    if (t == 0) {
        float S = 0.f, S2 = 0.f;
        #pragma unroll
        for (int i = 0; i < 8; i++) { S += ps[i]; S2 += ps2[i]; }
        float m = S / (float)D;
        s_mu = m;
        s_rs = rsqrtf(S2 / (float)D - m * m + LN_EPS);
    }
    __syncthreads();
    const float mu = s_mu, rs = s_rs;

    float4 g0 = *reinterpret_cast<const float4*>(gamma + t * 8);
    float4 g1 = *reinterpret_cast<const float4*>(gamma + t * 8 + 4);
    float4 b0 = *reinterpret_cast<const float4*>(beta  + t * 8);
    float4 b1 = *reinterpret_cast<const float4*>(beta  + t * 8 + 4);

    float xn[8] = {
        (v0.x - mu) * rs * g0.x + b0.x, (v0.y - mu) * rs * g0.y + b0.y,
        (v0.z - mu) * rs * g0.z + b0.z, (v0.w - mu) * rs * g0.w + b0.w,
        (v1.x - mu) * rs * g1.x + b1.x, (v1.y - mu) * rs * g1.y + b1.y,
        (v1.z - mu) * rs * g1.z + b1.z, (v1.w - mu) * rs * g1.w + b1.w };

    union { __nv_bfloat16 h[8]; uint4 u; } H, L;
    #pragma unroll
    for (int i = 0; i < 8; i++) {
        __nv_bfloat16 hi = __float2bfloat16(xn[i]);
        H.h[i] = hi;
        L.h[i] = __float2bfloat16(xn[i] - __bfloat162float(hi));
    }
    const size_t o = (size_t)row * D + t * 8;
    *reinterpret_cast<uint4*>(&g_Ahi[o]) = H.u;
    *reinterpret_cast<uint4*>(&g_Alo[o]) = L.u;
}

// ------------------------- Stage 2: W transpose + split -------------
__global__ __launch_bounds__(256)
void wsplit_kernel(const float* __restrict__ W, int K, int N) {
    __shared__ float tile[32][33];
    const int k0 = blockIdx.y * 32, n0 = blockIdx.x * 32;
    const int tx = threadIdx.x, ty = threadIdx.y;  // 32 x 8
    #pragma unroll
    for (int r = 0; r < 32; r += 8)
        tile[ty + r][tx] = W[(size_t)(k0 + ty + r) * N + n0 + tx];
    __syncthreads();
    #pragma unroll
    for (int r = 0; r < 32; r += 8) {
        const int n = n0 + ty + r, k = k0 + tx;
        float v = tile[tx][ty + r];
        __nv_bfloat16 hi = __float2bfloat16(v);
        g_Bhi[(size_t)n * K + k] = hi;
        g_Blo[(size_t)n * K + k] = __float2bfloat16(v - __bfloat162float(hi));
    }
}

// ------------------------- Stage 3: GEMM ----------------------------
static constexpr int BM = 128, BN = 256, BK = 32;
static constexpr int STAGES = 4;
static constexpr int THREADS = 512;
// per-stage layout: Ahi [0,8192) Alo [8192,16384) Bhi [16384,32768) Blo [32768,49152)
static constexpr int A_LO_OFF  = 8192;
static constexpr int B_OFF     = 16384;
static constexpr int B_LO_OFF  = 16384;   // relative to Bhi
static constexpr int STAGE_BYTES = 49152;
static constexpr int SMEM_TOTAL  = 1024 + STAGES * STAGE_BYTES;  // 197632

__global__ __launch_bounds__(THREADS, 1)
void ffn_mma_kernel(const float* __restrict__ x,
                    const float* __restrict__ bias,
                    float* __restrict__ out,
                    int K, int H) {
    extern __shared__ __align__(1024) uint8_t dynsmem[];
    uint32_t sb = smem_u32(dynsmem);
    sb = (sb + 1023) & ~1023u;

    const int t    = threadIdx.x;
    const int lane = t & 31;
    const int wid  = t >> 5;
    const int g    = lane >> 2;
    const int tg   = lane & 3;
    const int m0   = blockIdx.y * BM;
    const int n0   = blockIdx.x * BN;
    const int wm   = (wid >> 3) * 64;   // 0 or 64
    const int wn   = (wid & 7)  * 32;   // 0..224

    // ---- cp.async source pointers (one A row, two B rows per thread) ----
    const int ldrow = t >> 2;            // 0..127
    const int ldc   = t & 3;             // 16B chunk within 64B row
    const size_t aoff = (size_t)(m0 + ldrow) * K + ldc * 8;
    const size_t boff = (size_t)(n0 + ldrow) * K + ldc * 8;
    const __nv_bfloat16* pAhi = g_Ahi + aoff;
    const __nv_bfloat16* pAlo = g_Alo + aoff;
    const __nv_bfloat16* pBhi = g_Bhi + boff;
    const __nv_bfloat16* pBlo = g_Blo + boff;
    const size_t rstep = (size_t)128 * K;   // +128 rows (B second half)

    const uint32_t dstA = sb + swz((uint32_t)(ldrow * 64 + ldc * 16));
    const uint32_t dstB = sb + B_OFF + swz((uint32_t)(ldrow * 64 + ldc * 16));

    // ---- ldmatrix base addresses (stage 0, ks=0, hi buffers) ----
    const int matid = lane >> 3, r8 = lane & 7;
    uint32_t aAdr[4], bAdr[2];
    #pragma unroll
    for (int mt = 0; mt < 4; mt++) {
        const uint32_t m = wm + mt * 16 + (matid & 1) * 8 + r8;
        aAdr[mt] = sb + swz(m * 64 + (matid >> 1) * 16);
    }
    #pragma unroll
    for (int p = 0; p < 2; p++) {
        const uint32_t n = wn + p * 16 + (matid >> 1) * 8 + r8;
        bAdr[p] = sb + B_OFF + swz(n * 64 + (matid & 1) * 16);
    }

    float acc[4][4][4];
    #pragma unroll
    for (int mt = 0; mt < 4; mt++)
        #pragma unroll
        for (int nt = 0; nt < 4; nt++)
            #pragma unroll
            for (int r = 0; r < 4; r++) acc[mt][nt][r] = 0.f;

    const int NT = K / BK;   // 64

    // ---- pipeline prologue ----
    #pragma unroll
    for (int s = 0; s < STAGES - 1; s++) {
        const uint32_t so = s * STAGE_BYTES;
        const __nv_bfloat16* ah = pAhi + s * 32;
        const __nv_bfloat16* al = pAlo + s * 32;
        const __nv_bfloat16* bh = pBhi + s * 32;
        const __nv_bfloat16* bl = pBlo + s * 32;
        cp16(dstA + so,                   ah);
        cp16(dstA + so + A_LO_OFF,        al);
        cp16(dstB + so,                   bh);
        cp16(dstB + so + 8192,            bh + rstep);
        cp16(dstB + so + B_LO_OFF,        bl);
        cp16(dstB + so + B_LO_OFF + 8192, bl + rstep);
        asm volatile("cp.async.commit_group;" ::: "memory");
    }

    // ---- main loop ----
    for (int kt = 0; kt < NT; kt++) {
        asm volatile("cp.async.wait_group 2;" ::: "memory");
        __syncthreads();

        if (kt + STAGES - 1 < NT) {
            const int s = kt + STAGES - 1;
            const uint32_t so = (s & 3) * STAGE_BYTES;
            const __nv_bfloat16* ah = pAhi + s * 32;
            const __nv_bfloat16* al = pAlo + s * 32;
            const __nv_bfloat16* bh = pBhi + s * 32;
            const __nv_bfloat16* bl = pBlo + s * 32;
            cp16(dstA + so,                   ah);
            cp16(dstA + so + A_LO_OFF,        al);
            cp16(dstB + so,                   bh);
            cp16(dstB + so + 8192,            bh + rstep);
            cp16(dstB + so + B_LO_OFF,        bl);
            cp16(dstB + so + B_LO_OFF + 8192, bl + rstep);
        }
        asm volatile("cp.async.commit_group;" ::: "memory");

        const uint32_t so = (kt & 3) * STAGE_BYTES;

        #pragma unroll
        for (int ks = 0; ks < 2; ks++) {
            const uint32_t kx = ks * 32;   // bit-5 toggle, swizzle-transparent
            uint32_t bh[8], bl[8];
            #pragma unroll
            for (int p = 0; p < 2; p++) {
                const uint32_t a = (bAdr[p] + so) ^ kx;
                ldsm4(&bh[p * 4], a);
                ldsm4o<B_LO_OFF>(&bl[p * 4], a);
            }
            uint32_t ah[4][4], al[4][4];
            #pragma unroll
            for (int mt = 0; mt < 4; mt++) {
                const uint32_t a = (aAdr[mt] + so) ^ kx;
                ldsm4(ah[mt], a);
                ldsm4o<A_LO_OFF>(al[mt], a);
            }
            // product-outer ordering: same-acc MMAs are >=16 apart
            #pragma unroll
            for (int mt = 0; mt < 4; mt++)
                #pragma unroll
                for (int nt = 0; nt < 4; nt++)
                    mma16816(acc[mt][nt], ah[mt], &bh[nt * 2]);   // hi*hi
            #pragma unroll
            for (int mt = 0; mt < 4; mt++)
                #pragma unroll
                for (int nt = 0; nt < 4; nt++)
                    mma16816(acc[mt][nt], al[mt], &bh[nt * 2]);   // lo*hi
            #pragma unroll
            for (int mt = 0; mt < 4; mt++)
                #pragma unroll
                for (int nt = 0; nt < 4; nt++)
                    mma16816(acc[mt][nt], ah[mt], &bl[nt * 2]);   // hi*lo
        }
    }

    // ---- epilogue: bias + exact GELU + residual ----
    #pragma unroll
    for (int mt = 0; mt < 4; mt++) {
        #pragma unroll
        for (int half = 0; half < 2; half++) {
            const int m = m0 + wm + mt * 16 + g + half * 8;
            const float* xr = x + (size_t)m * H;
            float* orow = out + (size_t)m * H;
            #pragma unroll
            for (int nt = 0; nt < 4; nt++) {
                const int n = n0 + wn + nt * 8 + tg * 2;
                float c0 = acc[mt][nt][half * 2 + 0];
                float c1 = acc[mt][nt][half * 2 + 1];
                const float2 bb = *reinterpret_cast<const float2*>(bias + n);
                float h0 = c0 + bb.x, h1 = c1 + bb.y;
                h0 = 0.5f * h0 * (1.0f + erff(h0 * 0.70710678118654752f));
                h1 = 0.5f * h1 * (1.0f + erff(h1 * 0.70710678118654752f));
                const float2 xv = *reinterpret_cast<const float2*>(xr + n);
                float2 o;
                o.x = h0 + xv.x;
                o.y = h1 + xv.y;
                *reinterpret_cast<float2*>(orow + n) = o;
            }
        }
    }
}

// ------------------------- host side ---------------------------------
extern "C" void kernel_launch(void* const* d_in, const int* in_sizes, int n_in,
                              void* d_out, int out_size) {
    const float* x     = (const float*)d_in[0];
    const float* gamma = (const float*)d_in[1];
    const float* beta  = (const float*)d_in[2];
    const float* W     = (const float*)d_in[3];
    const float* bias  = (const float*)d_in[4];
    float* out = (float*)d_out;

    const int D = in_sizes[1];
    const int H = in_sizes[4];
    const int M = in_sizes[0] / D;

    ln_split_kernel<<<M, 256>>>(x, gamma, beta, D);

    dim3 wgrid(H / 32, D / 32);
    wsplit_kernel<<<wgrid, dim3(32, 8)>>>(W, D, H);

    cudaFuncSetAttribute(ffn_mma_kernel,
                         cudaFuncAttributeMaxDynamicSharedMemorySize, SMEM_TOTAL);
    dim3 ggrid(H / BN, M / BM);
    ffn_mma_kernel<<<ggrid, THREADS, SMEM_TOTAL>>>(x, bias, out, D, H);
}

// round 7
// speedup vs baseline: 2.8922x; 1.0309x over previous
#include <cuda_runtime.h>
#include <cuda_bf16.h>
#include <cstdint>

// =====================================================================
// Fused LayerNorm -> Linear -> exact GELU -> residual
//   x [M=32768, D=2048] fp32, W [D, H=2048] fp32, out [M, H] fp32
// GEMM via mma.sync.m16n8k16 bf16 with hi/lo split:
//   D = Ahi*Bhi + Alo*Bhi + Ahi*Blo   (fp32 accumulate)
// R7: BK=64 (128B SW128 rows), 2-stage double buffer -> half the
//     per-iteration barrier/issue overhead.
// =====================================================================

#define LN_EPS 1e-5f
static constexpr int MROWS = 32768;
static constexpr int DDIM  = 2048;

__device__ __align__(1024) __nv_bfloat16 g_Ahi[(size_t)MROWS * DDIM];
__device__ __align__(1024) __nv_bfloat16 g_Alo[(size_t)MROWS * DDIM];
__device__ __align__(1024) __nv_bfloat16 g_Bhi[(size_t)DDIM * DDIM];
__device__ __align__(1024) __nv_bfloat16 g_Blo[(size_t)DDIM * DDIM];

// ------------------------- helpers ----------------------------------
__device__ __forceinline__ uint32_t smem_u32(const void* p) {
    uint32_t a;
    asm("{ .reg .u64 t; cvta.to.shared.u64 t, %1; cvt.u32.u64 %0, t; }"
        : "=r"(a) : "l"(p));
    return a;
}
__device__ __forceinline__ uint32_t swz(uint32_t off) {   // SW128: bits[6:4] ^= bits[9:7]
    return off ^ ((off >> 3) & 0x70u);
}
__device__ __forceinline__ void cp16(uint32_t dst, const void* src) {
    asm volatile("cp.async.cg.shared.global [%0], [%1], 16;" :: "r"(dst), "l"(src));
}
__device__ __forceinline__ void ldsm4(uint32_t* r, uint32_t a) {
    asm volatile("ldmatrix.sync.aligned.m8n8.x4.shared.b16 {%0,%1,%2,%3}, [%4];"
        : "=r"(r[0]), "=r"(r[1]), "=r"(r[2]), "=r"(r[3]) : "r"(a));
}
template <int IMM>
__device__ __forceinline__ void ldsm4o(uint32_t* r, uint32_t a) {
    asm volatile("ldmatrix.sync.aligned.m8n8.x4.shared.b16 {%0,%1,%2,%3}, [%4+%5];"
        : "=r"(r[0]), "=r"(r[1]), "=r"(r[2]), "=r"(r[3]) : "r"(a), "n"(IMM));
}
__device__ __forceinline__ void mma16816(float* c, const uint32_t* a, const uint32_t* b) {
    asm volatile(
        "mma.sync.aligned.m16n8k16.row.col.f32.bf16.bf16.f32 "
        "{%0,%1,%2,%3}, {%4,%5,%6,%7}, {%8,%9}, {%0,%1,%2,%3};"
        : "+f"(c[0]), "+f"(c[1]), "+f"(c[2]), "+f"(c[3])
        : "r"(a[0]), "r"(a[1]), "r"(a[2]), "r"(a[3]), "r"(b[0]), "r"(b[1]));
}

// ------------------------- Stage 1: LN + split A --------------------
__global__ __launch_bounds__(256)
void ln_split_kernel(const float* __restrict__ x,
                     const float* __restrict__ gamma,
                     const float* __restrict__ beta, int D) {
    const int row = blockIdx.x;
    const int t = threadIdx.x;
    const float* xr = x + (size_t)row * D;

    float4 v0 = *reinterpret_cast<const float4*>(xr + t * 8);
    float4 v1 = *reinterpret_cast<const float4*>(xr + t * 8 + 4);

    float s  = v0.x + v0.y + v0.z + v0.w + v1.x + v1.y + v1.z + v1.w;
    float s2 = v0.x*v0.x + v0.y*v0.y + v0.z*v0.z + v0.w*v0.w
             + v1.x*v1.x + v1.y*v1.y + v1.z*v1.z + v1.w*v1.w;
    #pragma unroll
    for (int o = 16; o > 0; o >>= 1) {
        s  += __shfl_down_sync(0xFFFFFFFFu, s, o);
        s2 += __shfl_down_sync(0xFFFFFFFFu, s2, o);
    }
    __shared__ float ps[8], ps2[8], s_mu, s_rs;
    const int wid = t >> 5, lane = t & 31;
    if (lane == 0) { ps[wid] = s; ps2[wid] = s2; }
    __syncthreads();
    if (t == 0) {
        float S = 0.f, S2 = 0.f;
        #pragma unroll
        for (int i = 0; i < 8; i++) { S += ps[i]; S2 += ps2[i]; }
        float m = S / (float)D;
        s_mu = m;
        s_rs = rsqrtf(S2 / (float)D - m * m + LN_EPS);
    }
    __syncthreads();
    const float mu = s_mu, rs = s_rs;

    float4 g0 = *reinterpret_cast<const float4*>(gamma + t * 8);
    float4 g1 = *reinterpret_cast<const float4*>(gamma + t * 8 + 4);
    float4 b0 = *reinterpret_cast<const float4*>(beta  + t * 8);
    float4 b1 = *reinterpret_cast<const float4*>(beta  + t * 8 + 4);

    float xn[8] = {
        (v0.x - mu) * rs * g0.x + b0.x, (v0.y - mu) * rs * g0.y + b0.y,
        (v0.z - mu) * rs * g0.z + b0.z, (v0.w - mu) * rs * g0.w + b0.w,
        (v1.x - mu) * rs * g1.x + b1.x, (v1.y - mu) * rs * g1.y + b1.y,
        (v1.z - mu) * rs * g1.z + b1.z, (v1.w - mu) * rs * g1.w + b1.w };

    union { __nv_bfloat16 h[8]; uint4 u; } H, L;
    #pragma unroll
    for (int i = 0; i < 8; i++) {
        __nv_bfloat16 hi = __float2bfloat16(xn[i]);
        H.h[i] = hi;
        L.h[i] = __float2bfloat16(xn[i] - __bfloat162float(hi));
    }
    const size_t o = (size_t)row * D + t * 8;
    *reinterpret_cast<uint4*>(&g_Ahi[o]) = H.u;
    *reinterpret_cast<uint4*>(&g_Alo[o]) = L.u;
}

// ------------------------- Stage 2: W transpose + split -------------
__global__ __launch_bounds__(256)
void wsplit_kernel(const float* __restrict__ W, int K, int N) {
    __shared__ float tile[32][33];
    const int k0 = blockIdx.y * 32, n0 = blockIdx.x * 32;
    const int tx = threadIdx.x, ty = threadIdx.y;  // 32 x 8
    #pragma unroll
    for (int r = 0; r < 32; r += 8)
        tile[ty + r][tx] = W[(size_t)(k0 + ty + r) * N + n0 + tx];
    __syncthreads();
    #pragma unroll
    for (int r = 0; r < 32; r += 8) {
        const int n = n0 + ty + r, k = k0 + tx;
        float v = tile[tx][ty + r];
        __nv_bfloat16 hi = __float2bfloat16(v);
        g_Bhi[(size_t)n * K + k] = hi;
        g_Blo[(size_t)n * K + k] = __float2bfloat16(v - __bfloat162float(hi));
    }
}

// ------------------------- Stage 3: GEMM ----------------------------
static constexpr int BM = 128, BN = 256, BK = 64;
static constexpr int STAGES = 2;
static constexpr int THREADS = 512;
// per-stage (128B rows): Ahi [0,16K) Alo [16K,32K) Bhi [32K,64K) Blo [64K,96K)
static constexpr int A_LO_OFF  = 16384;
static constexpr int B_OFF     = 32768;
static constexpr int B_LO_OFF  = 32768;   // relative to Bhi
static constexpr int STAGE_BYTES = 98304;
static constexpr int SMEM_TOTAL  = 1024 + STAGES * STAGE_BYTES;  // 197632

__global__ __launch_bounds__(THREADS, 1)
void ffn_mma_kernel(const float* __restrict__ x,
                    const float* __restrict__ bias,
                    float* __restrict__ out,
                    int K, int H) {
    extern __shared__ __align__(1024) uint8_t dynsmem[];
    uint32_t sb = smem_u32(dynsmem);
    sb = (sb + 1023) & ~1023u;

    const int t    = threadIdx.x;
    const int lane = t & 31;
    const int wid  = t >> 5;
    const int g    = lane >> 2;
    const int tg   = lane & 3;
    const int m0   = blockIdx.y * BM;
    const int n0   = blockIdx.x * BN;
    const int wm   = (wid >> 3) * 64;   // 0 or 64
    const int wn   = (wid & 7)  * 32;   // 0..224

    // ---- cp.async: thread t handles chunk idx = t + i*512 ----
    //   row = idx>>3 (128B rows / 8 chunks), col16 = idx&7
    const int ldrow = t >> 3;            // 0..63
    const int ldc   = t & 7;             // 16B chunk within 128B row
    const size_t aoff = (size_t)(m0 + ldrow) * K + ldc * 8;
    const size_t boff = (size_t)(n0 + ldrow) * K + ldc * 8;
    const __nv_bfloat16* pAhi = g_Ahi + aoff;
    const __nv_bfloat16* pAlo = g_Alo + aoff;
    const __nv_bfloat16* pBhi = g_Bhi + boff;
    const __nv_bfloat16* pBlo = g_Blo + boff;
    const size_t rstep = (size_t)64 * K;   // +64 rows

    const uint32_t dstA = sb + swz((uint32_t)(ldrow * 128 + ldc * 16));
    const uint32_t dstB = sb + B_OFF + swz((uint32_t)(ldrow * 128 + ldc * 16));

    // ---- ldmatrix base addresses (stage 0, ks=0, hi buffers) ----
    const int matid = lane >> 3, r8 = lane & 7;
    uint32_t aAdr[4], bAdr[2];
    #pragma unroll
    for (int mt = 0; mt < 4; mt++) {
        const uint32_t m = wm + mt * 16 + (matid & 1) * 8 + r8;
        aAdr[mt] = sb + swz(m * 128 + (matid >> 1) * 16);
    }
    #pragma unroll
    for (int p = 0; p < 2; p++) {
        const uint32_t n = wn + p * 16 + (matid >> 1) * 8 + r8;
        bAdr[p] = sb + B_OFF + swz(n * 128 + (matid & 1) * 16);
    }

    float acc[4][4][4];
    #pragma unroll
    for (int mt = 0; mt < 4; mt++)
        #pragma unroll
        for (int nt = 0; nt < 4; nt++)
            #pragma unroll
            for (int r = 0; r < 4; r++) acc[mt][nt][r] = 0.f;

    const int NT = K / BK;   // 32

    // ---- load one stage (kt-th k-slice into buffer buf) ----
    auto load_stage = [&](int kt, int buf) {
        const uint32_t so = buf * STAGE_BYTES;
        const int kc = kt * BK;
        const __nv_bfloat16* ah = pAhi + kc;
        const __nv_bfloat16* al = pAlo + kc;
        const __nv_bfloat16* bh = pBhi + kc;
        const __nv_bfloat16* bl = pBlo + kc;
        cp16(dstA + so,                   ah);
        cp16(dstA + so + 8192,            ah + rstep);
        cp16(dstA + so + A_LO_OFF,        al);
        cp16(dstA + so + A_LO_OFF + 8192, al + rstep);
        #pragma unroll
        for (int i = 0; i < 4; i++) {
            cp16(dstB + so + i * 8192,            bh + i * rstep);
            cp16(dstB + so + B_LO_OFF + i * 8192, bl + i * rstep);
        }
    };

    // ---- prologue: stage 0 ----
    load_stage(0, 0);
    asm volatile("cp.async.commit_group;" ::: "memory");

    // ---- main loop (2-stage double buffer, prefetch distance 1) ----
    for (int kt = 0; kt < NT; kt++) {
        const int cur = kt & 1;

        if (kt + 1 < NT) load_stage(kt + 1, cur ^ 1);
        asm volatile("cp.async.commit_group;" ::: "memory");

        asm volatile("cp.async.wait_group 1;" ::: "memory");
        __syncthreads();

        const uint32_t so = cur * STAGE_BYTES;

        #pragma unroll
        for (int ks = 0; ks < 4; ks++) {
            const uint32_t kx = ks * 32;   // XOR step, swizzle-transparent
            uint32_t bh[8], bl[8];
            #pragma unroll
            for (int p = 0; p < 2; p++) {
                const uint32_t a = (bAdr[p] + so) ^ kx;
                ldsm4(&bh[p * 4], a);
                ldsm4o<B_LO_OFF>(&bl[p * 4], a);
            }
            uint32_t ah[4][4], al[4][4];
            #pragma unroll
            for (int mt = 0; mt < 4; mt++) {
                const uint32_t a = (aAdr[mt] + so) ^ kx;
                ldsm4(ah[mt], a);
                ldsm4o<A_LO_OFF>(al[mt], a);
            }
            // product-outer ordering: same-acc MMAs are >=16 apart
            #pragma unroll
            for (int mt = 0; mt < 4; mt++)
                #pragma unroll
                for (int nt = 0; nt < 4; nt++)
                    mma16816(acc[mt][nt], ah[mt], &bh[nt * 2]);   // hi*hi
            #pragma unroll
            for (int mt = 0; mt < 4; mt++)
                #pragma unroll
                for (int nt = 0; nt < 4; nt++)
                    mma16816(acc[mt][nt], al[mt], &bh[nt * 2]);   // lo*hi
            #pragma unroll
            for (int mt = 0; mt < 4; mt++)
                #pragma unroll
                for (int nt = 0; nt < 4; nt++)
                    mma16816(acc[mt][nt], ah[mt], &bl[nt * 2]);   // hi*lo
        }
        __syncthreads();   // all reads of stage cur done before kt+1 overwrites it
    }

    // ---- epilogue: bias + exact GELU + residual ----
    #pragma unroll
    for (int mt = 0; mt < 4; mt++) {
        #pragma unroll
        for (int half = 0; half < 2; half++) {
            const int m = m0 + wm + mt * 16 + g + half * 8;
            const float* xr = x + (size_t)m * H;
            float* orow = out + (size_t)m * H;
            #pragma unroll
            for (int nt = 0; nt < 4; nt++) {
                const int n = n0 + wn + nt * 8 + tg * 2;
                float c0 = acc[mt][nt][half * 2 + 0];
                float c1 = acc[mt][nt][half * 2 + 1];
                const float2 bb = *reinterpret_cast<const float2*>(bias + n);
                float h0 = c0 + bb.x, h1 = c1 + bb.y;
                h0 = 0.5f * h0 * (1.0f + erff(h0 * 0.70710678118654752f));
                h1 = 0.5f * h1 * (1.0f + erff(h1 * 0.70710678118654752f));
                const float2 xv = *reinterpret_cast<const float2*>(xr + n);
                float2 o;
                o.x = h0 + xv.x;
                o.y = h1 + xv.y;
                *reinterpret_cast<float2*>(orow + n) = o;
            }
        }
    }
}

// ------------------------- host side ---------------------------------
extern "C" void kernel_launch(void* const* d_in, const int* in_sizes, int n_in,
                              void* d_out, int out_size) {
    const float* x     = (const float*)d_in[0];
    const float* gamma = (const float*)d_in[1];
    const float* beta  = (const float*)d_in[2];
    const float* W     = (const float*)d_in[3];
    const float* bias  = (const float*)d_in[4];
    float* out = (float*)d_out;

    const int D = in_sizes[1];
    const int H = in_sizes[4];
    const int M = in_sizes[0] / D;

    ln_split_kernel<<<M, 256>>>(x, gamma, beta, D);

    dim3 wgrid(H / 32, D / 32);
    wsplit_kernel<<<wgrid, dim3(32, 8)>>>(W, D, H);

    cudaFuncSetAttribute(ffn_mma_kernel,
                         cudaFuncAttributeMaxDynamicSharedMemorySize, SMEM_TOTAL);
    dim3 ggrid(H / BN, M / BM);
    ffn_mma_kernel<<<ggrid, THREADS, SMEM_TOTAL>>>(x, bias, out, D, H);
}

// round 8
// speedup vs baseline: 4.0584x; 1.4032x over previous
#include <cuda_runtime.h>
#include <cuda_fp16.h>
#include <cstdint>

// =====================================================================
// Fused LayerNorm -> Linear -> exact GELU -> residual
//   x [M=32768, D=2048] fp32, W [D, H=2048] fp32, out [M, H] fp32
// R8: fp16 two-product split (fp16 mantissa 10 bits):
//   D = Ahi*B + Alo*B      (fp32 accumulate, B rounded to fp16 once)
//   error dominated by B fp16 rounding ~2.8e-4 rel  (gate: 1e-3)
// GEMM: mma.sync.m16n8k16.f32.f16.f16.f32, BK=64, 2-stage cp.async,
//       512 threads, warp tile 64x32, SW128-swizzled smem.
// =====================================================================

#define LN_EPS 1e-5f
static constexpr int MROWS = 32768;
static constexpr int DDIM  = 2048;

__device__ __align__(1024) __half g_Ahi[(size_t)MROWS * DDIM];
__device__ __align__(1024) __half g_Alo[(size_t)MROWS * DDIM];
__device__ __align__(1024) __half g_B  [(size_t)DDIM * DDIM];   // [N, K]

// ------------------------- helpers ----------------------------------
__device__ __forceinline__ uint32_t smem_u32(const void* p) {
    uint32_t a;
    asm("{ .reg .u64 t; cvta.to.shared.u64 t, %1; cvt.u32.u64 %0, t; }"
        : "=r"(a) : "l"(p));
    return a;
}
__device__ __forceinline__ uint32_t swz(uint32_t off) {   // SW128: bits[6:4] ^= bits[9:7]
    return off ^ ((off >> 3) & 0x70u);
}
__device__ __forceinline__ void cp16(uint32_t dst, const void* src) {
    asm volatile("cp.async.cg.shared.global [%0], [%1], 16;" :: "r"(dst), "l"(src));
}
__device__ __forceinline__ void ldsm4(uint32_t* r, uint32_t a) {
    asm volatile("ldmatrix.sync.aligned.m8n8.x4.shared.b16 {%0,%1,%2,%3}, [%4];"
        : "=r"(r[0]), "=r"(r[1]), "=r"(r[2]), "=r"(r[3]) : "r"(a));
}
template <int IMM>
__device__ __forceinline__ void ldsm4o(uint32_t* r, uint32_t a) {
    asm volatile("ldmatrix.sync.aligned.m8n8.x4.shared.b16 {%0,%1,%2,%3}, [%4+%5];"
        : "=r"(r[0]), "=r"(r[1]), "=r"(r[2]), "=r"(r[3]) : "r"(a), "n"(IMM));
}
__device__ __forceinline__ void mma16816(float* c, const uint32_t* a, const uint32_t* b) {
    asm volatile(
        "mma.sync.aligned.m16n8k16.row.col.f32.f16.f16.f32 "
        "{%0,%1,%2,%3}, {%4,%5,%6,%7}, {%8,%9}, {%0,%1,%2,%3};"
        : "+f"(c[0]), "+f"(c[1]), "+f"(c[2]), "+f"(c[3])
        : "r"(a[0]), "r"(a[1]), "r"(a[2]), "r"(a[3]), "r"(b[0]), "r"(b[1]));
}

// ------------------------- Stage 1: LN + fp16 split A ---------------
__global__ __launch_bounds__(256)
void ln_split_kernel(const float* __restrict__ x,
                     const float* __restrict__ gamma,
                     const float* __restrict__ beta, int D) {
    const int row = blockIdx.x;
    const int t = threadIdx.x;
    const float* xr = x + (size_t)row * D;

    float4 v0 = *reinterpret_cast<const float4*>(xr + t * 8);
    float4 v1 = *reinterpret_cast<const float4*>(xr + t * 8 + 4);

    float s  = v0.x + v0.y + v0.z + v0.w + v1.x + v1.y + v1.z + v1.w;
    float s2 = v0.x*v0.x + v0.y*v0.y + v0.z*v0.z + v0.w*v0.w
             + v1.x*v1.x + v1.y*v1.y + v1.z*v1.z + v1.w*v1.w;
    #pragma unroll
    for (int o = 16; o > 0; o >>= 1) {
        s  += __shfl_down_sync(0xFFFFFFFFu, s, o);
        s2 += __shfl_down_sync(0xFFFFFFFFu, s2, o);
    }
    __shared__ float ps[8], ps2[8], s_mu, s_rs;
    const int wid = t >> 5, lane = t & 31;
    if (lane == 0) { ps[wid] = s; ps2[wid] = s2; }
    __syncthreads();
    if (t == 0) {
        float S = 0.f, S2 = 0.f;
        #pragma unroll
        for (int i = 0; i < 8; i++) { S += ps[i]; S2 += ps2[i]; }
        float m = S / (float)D;
        s_mu = m;
        s_rs = rsqrtf(S2 / (float)D - m * m + LN_EPS);
    }
    __syncthreads();
    const float mu = s_mu, rs = s_rs;

    float4 g0 = *reinterpret_cast<const float4*>(gamma + t * 8);
    float4 g1 = *reinterpret_cast<const float4*>(gamma + t * 8 + 4);
    float4 b0 = *reinterpret_cast<const float4*>(beta  + t * 8);
    float4 b1 = *reinterpret_cast<const float4*>(beta  + t * 8 + 4);

    float xn[8] = {
        (v0.x - mu) * rs * g0.x + b0.x, (v0.y - mu) * rs * g0.y + b0.y,
        (v0.z - mu) * rs * g0.z + b0.z, (v0.w - mu) * rs * g0.w + b0.w,
        (v1.x - mu) * rs * g1.x + b1.x, (v1.y - mu) * rs * g1.y + b1.y,
        (v1.z - mu) * rs * g1.z + b1.z, (v1.w - mu) * rs * g1.w + b1.w };

    union { __half h[8]; uint4 u; } H, L;
    #pragma unroll
    for (int i = 0; i < 8; i++) {
        __half hi = __float2half(xn[i]);
        H.h[i] = hi;
        L.h[i] = __float2half(xn[i] - __half2float(hi));
    }
    const size_t o = (size_t)row * D + t * 8;
    *reinterpret_cast<uint4*>(&g_Ahi[o]) = H.u;
    *reinterpret_cast<uint4*>(&g_Alo[o]) = L.u;
}

// ------------------------- Stage 2: W transpose -> fp16 -------------
__global__ __launch_bounds__(256)
void wsplit_kernel(const float* __restrict__ W, int K, int N) {
    __shared__ float tile[32][33];
    const int k0 = blockIdx.y * 32, n0 = blockIdx.x * 32;
    const int tx = threadIdx.x, ty = threadIdx.y;  // 32 x 8
    #pragma unroll
    for (int r = 0; r < 32; r += 8)
        tile[ty + r][tx] = W[(size_t)(k0 + ty + r) * N + n0 + tx];
    __syncthreads();
    #pragma unroll
    for (int r = 0; r < 32; r += 8) {
        const int n = n0 + ty + r, k = k0 + tx;
        g_B[(size_t)n * K + k] = __float2half(tile[tx][ty + r]);
    }
}

// ------------------------- Stage 3: GEMM ----------------------------
static constexpr int BM = 128, BN = 256, BK = 64;
static constexpr int THREADS = 512;
// per-stage (128B rows): Ahi [0,16K) Alo [16K,32K) B [32K,64K)
static constexpr int A_LO_OFF  = 16384;
static constexpr int B_OFF     = 32768;
static constexpr int STAGE_BYTES = 65536;
static constexpr int SMEM_TOTAL  = 1024 + 2 * STAGE_BYTES;  // 132096

__global__ __launch_bounds__(THREADS, 1)
void ffn_mma_kernel(const float* __restrict__ x,
                    const float* __restrict__ bias,
                    float* __restrict__ out,
                    int K, int H) {
    extern __shared__ __align__(1024) uint8_t dynsmem[];
    uint32_t sb = smem_u32(dynsmem);
    sb = (sb + 1023) & ~1023u;

    const int t    = threadIdx.x;
    const int lane = t & 31;
    const int wid  = t >> 5;
    const int g    = lane >> 2;
    const int tg   = lane & 3;
    const int m0   = blockIdx.y * BM;
    const int n0   = blockIdx.x * BN;
    const int wm   = (wid >> 3) * 64;   // 0 or 64
    const int wn   = (wid & 7)  * 32;   // 0..224

    // ---- cp.async: 128B rows, 8 x 16B chunks/row ----
    const int ldrow = t >> 3;            // 0..63
    const int ldc   = t & 7;             // chunk within row
    const size_t aoff = (size_t)(m0 + ldrow) * K + ldc * 8;
    const size_t boff = (size_t)(n0 + ldrow) * K + ldc * 8;
    const __half* pAhi = g_Ahi + aoff;
    const __half* pAlo = g_Alo + aoff;
    const __half* pB   = g_B   + boff;
    const size_t rstep = (size_t)64 * K;   // +64 rows

    const uint32_t dstA = sb + swz((uint32_t)(ldrow * 128 + ldc * 16));
    const uint32_t dstB = sb + B_OFF + swz((uint32_t)(ldrow * 128 + ldc * 16));

    // ---- ldmatrix base addresses (stage 0, ks=0) ----
    const int matid = lane >> 3, r8 = lane & 7;
    uint32_t aAdr[4], bAdr[2];
    #pragma unroll
    for (int mt = 0; mt < 4; mt++) {
        const uint32_t m = wm + mt * 16 + (matid & 1) * 8 + r8;
        aAdr[mt] = sb + swz(m * 128 + (matid >> 1) * 16);
    }
    #pragma unroll
    for (int p = 0; p < 2; p++) {
        const uint32_t n = wn + p * 16 + (matid >> 1) * 8 + r8;
        bAdr[p] = sb + B_OFF + swz(n * 128 + (matid & 1) * 16);
    }

    float acc[4][4][4];
    #pragma unroll
    for (int mt = 0; mt < 4; mt++)
        #pragma unroll
        for (int nt = 0; nt < 4; nt++)
            #pragma unroll
            for (int r = 0; r < 4; r++) acc[mt][nt][r] = 0.f;

    const int NT = K / BK;   // 32

    auto load_stage = [&](int kt, int buf) {
        const uint32_t so = buf * STAGE_BYTES;
        const int kc = kt * BK;
        const __half* ah = pAhi + kc;
        const __half* al = pAlo + kc;
        const __half* b  = pB   + kc;
        cp16(dstA + so,                   ah);
        cp16(dstA + so + 8192,            ah + rstep);
        cp16(dstA + so + A_LO_OFF,        al);
        cp16(dstA + so + A_LO_OFF + 8192, al + rstep);
        #pragma unroll
        for (int i = 0; i < 4; i++)
            cp16(dstB + so + i * 8192, b + i * rstep);
    };

    load_stage(0, 0);
    asm volatile("cp.async.commit_group;" ::: "memory");

    for (int kt = 0; kt < NT; kt++) {
        const int cur = kt & 1;

        if (kt + 1 < NT) load_stage(kt + 1, cur ^ 1);
        asm volatile("cp.async.commit_group;" ::: "memory");

        asm volatile("cp.async.wait_group 1;" ::: "memory");
        __syncthreads();

        const uint32_t so = cur * STAGE_BYTES;

        #pragma unroll
        for (int ks = 0; ks < 4; ks++) {
            const uint32_t kx = ks * 32;   // XOR step, swizzle-transparent
            uint32_t bh[8];
            #pragma unroll
            for (int p = 0; p < 2; p++)
                ldsm4(&bh[p * 4], (bAdr[p] + so) ^ kx);
            uint32_t ah[4][4], al[4][4];
            #pragma unroll
            for (int mt = 0; mt < 4; mt++) {
                const uint32_t a = (aAdr[mt] + so) ^ kx;
                ldsm4(ah[mt], a);
                ldsm4o<A_LO_OFF>(al[mt], a);
            }
            // product-outer: same-acc MMAs are 16 apart
            #pragma unroll
            for (int mt = 0; mt < 4; mt++)
                #pragma unroll
                for (int nt = 0; nt < 4; nt++)
                    mma16816(acc[mt][nt], ah[mt], &bh[nt * 2]);   // hi*B
            #pragma unroll
            for (int mt = 0; mt < 4; mt++)
                #pragma unroll
                for (int nt = 0; nt < 4; nt++)
                    mma16816(acc[mt][nt], al[mt], &bh[nt * 2]);   // lo*B
        }
        __syncthreads();
    }

    // ---- epilogue: bias + exact GELU + residual ----
    #pragma unroll
    for (int mt = 0; mt < 4; mt++) {
        #pragma unroll
        for (int half = 0; half < 2; half++) {
            const int m = m0 + wm + mt * 16 + g + half * 8;
            const float* xr = x + (size_t)m * H;
            float* orow = out + (size_t)m * H;
            #pragma unroll
            for (int nt = 0; nt < 4; nt++) {
                const int n = n0 + wn + nt * 8 + tg * 2;
                float c0 = acc[mt][nt][half * 2 + 0];
                float c1 = acc[mt][nt][half * 2 + 1];
                const float2 bb = *reinterpret_cast<const float2*>(bias + n);
                float h0 = c0 + bb.x, h1 = c1 + bb.y;
                h0 = 0.5f * h0 * (1.0f + erff(h0 * 0.70710678118654752f));
                h1 = 0.5f * h1 * (1.0f + erff(h1 * 0.70710678118654752f));
                const float2 xv = *reinterpret_cast<const float2*>(xr + n);
                float2 o;
                o.x = h0 + xv.x;
                o.y = h1 + xv.y;
                *reinterpret_cast<float2*>(orow + n) = o;
            }
        }
    }
}

// ------------------------- host side ---------------------------------
extern "C" void kernel_launch(void* const* d_in, const int* in_sizes, int n_in,
                              void* d_out, int out_size) {
    const float* x     = (const float*)d_in[0];
    const float* gamma = (const float*)d_in[1];
    const float* beta  = (const float*)d_in[2];
    const float* W     = (const float*)d_in[3];
    const float* bias  = (const float*)d_in[4];
    float* out = (float*)d_out;

    const int D = in_sizes[1];
    const int H = in_sizes[4];
    const int M = in_sizes[0] / D;

    ln_split_kernel<<<M, 256>>>(x, gamma, beta, D);

    dim3 wgrid(H / 32, D / 32);
    wsplit_kernel<<<wgrid, dim3(32, 8)>>>(W, D, H);

    cudaFuncSetAttribute(ffn_mma_kernel,
                         cudaFuncAttributeMaxDynamicSharedMemorySize, SMEM_TOTAL);
    dim3 ggrid(H / BN, M / BM);
    ffn_mma_kernel<<<ggrid, THREADS, SMEM_TOTAL>>>(x, bias, out, D, H);
}

// round 9
// speedup vs baseline: 6.4075x; 1.5788x over previous
#include <cuda_runtime.h>
#include <cuda_fp16.h>
#include <cstdint>

// =====================================================================
// Fused LayerNorm -> Linear -> exact GELU -> residual
//   x [M=32768, D=2048] fp32, W [D, H=2048] fp32, out [M, H] fp32
// R9: single-product pure fp16 GEMM:
//   D = A_fp16 * B_fp16   (fp32 accumulate)
//   error: A-rounding + B-rounding, predicted rel_err ~1.7e-4 (gate 1e-3)
// GEMM: mma.sync.m16n8k16.f32.f16.f16.f32, BK=64, 2-stage cp.async,
//       512 threads, warp tile 64x32, SW128-swizzled smem.
// =====================================================================

#define LN_EPS 1e-5f
static constexpr int MROWS = 32768;
static constexpr int DDIM  = 2048;

__device__ __align__(1024) __half g_A[(size_t)MROWS * DDIM];   // LN(x) in fp16
__device__ __align__(1024) __half g_B[(size_t)DDIM * DDIM];    // W^T  in fp16 [N,K]

// ------------------------- helpers ----------------------------------
__device__ __forceinline__ uint32_t smem_u32(const void* p) {
    uint32_t a;
    asm("{ .reg .u64 t; cvta.to.shared.u64 t, %1; cvt.u32.u64 %0, t; }"
        : "=r"(a) : "l"(p));
    return a;
}
__device__ __forceinline__ uint32_t swz(uint32_t off) {   // SW128: bits[6:4] ^= bits[9:7]
    return off ^ ((off >> 3) & 0x70u);
}
__device__ __forceinline__ void cp16(uint32_t dst, const void* src) {
    asm volatile("cp.async.cg.shared.global [%0], [%1], 16;" :: "r"(dst), "l"(src));
}
__device__ __forceinline__ void ldsm4(uint32_t* r, uint32_t a) {
    asm volatile("ldmatrix.sync.aligned.m8n8.x4.shared.b16 {%0,%1,%2,%3}, [%4];"
        : "=r"(r[0]), "=r"(r[1]), "=r"(r[2]), "=r"(r[3]) : "r"(a));
}
__device__ __forceinline__ void mma16816(float* c, const uint32_t* a, const uint32_t* b) {
    asm volatile(
        "mma.sync.aligned.m16n8k16.row.col.f32.f16.f16.f32 "
        "{%0,%1,%2,%3}, {%4,%5,%6,%7}, {%8,%9}, {%0,%1,%2,%3};"
        : "+f"(c[0]), "+f"(c[1]), "+f"(c[2]), "+f"(c[3])
        : "r"(a[0]), "r"(a[1]), "r"(a[2]), "r"(a[3]), "r"(b[0]), "r"(b[1]));
}

// ------------------------- Stage 1: LN -> fp16 ----------------------
__global__ __launch_bounds__(256)
void ln_split_kernel(const float* __restrict__ x,
                     const float* __restrict__ gamma,
                     const float* __restrict__ beta, int D) {
    const int row = blockIdx.x;
    const int t = threadIdx.x;
    const float* xr = x + (size_t)row * D;

    float4 v0 = *reinterpret_cast<const float4*>(xr + t * 8);
    float4 v1 = *reinterpret_cast<const float4*>(xr + t * 8 + 4);

    float s  = v0.x + v0.y + v0.z + v0.w + v1.x + v1.y + v1.z + v1.w;
    float s2 = v0.x*v0.x + v0.y*v0.y + v0.z*v0.z + v0.w*v0.w
             + v1.x*v1.x + v1.y*v1.y + v1.z*v1.z + v1.w*v1.w;
    #pragma unroll
    for (int o = 16; o > 0; o >>= 1) {
        s  += __shfl_down_sync(0xFFFFFFFFu, s, o);
        s2 += __shfl_down_sync(0xFFFFFFFFu, s2, o);
    }
    __shared__ float ps[8], ps2[8], s_mu, s_rs;
    const int wid = t >> 5, lane = t & 31;
    if (lane == 0) { ps[wid] = s; ps2[wid] = s2; }
    __syncthreads();
    if (t == 0) {
        float S = 0.f, S2 = 0.f;
        #pragma unroll
        for (int i = 0; i < 8; i++) { S += ps[i]; S2 += ps2[i]; }
        float m = S / (float)D;
        s_mu = m;
        s_rs = rsqrtf(S2 / (float)D - m * m + LN_EPS);
    }
    __syncthreads();
    const float mu = s_mu, rs = s_rs;

    float4 g0 = *reinterpret_cast<const float4*>(gamma + t * 8);
    float4 g1 = *reinterpret_cast<const float4*>(gamma + t * 8 + 4);
    float4 b0 = *reinterpret_cast<const float4*>(beta  + t * 8);
    float4 b1 = *reinterpret_cast<const float4*>(beta  + t * 8 + 4);

    float xn[8] = {
        (v0.x - mu) * rs * g0.x + b0.x, (v0.y - mu) * rs * g0.y + b0.y,
        (v0.z - mu) * rs * g0.z + b0.z, (v0.w - mu) * rs * g0.w + b0.w,
        (v1.x - mu) * rs * g1.x + b1.x, (v1.y - mu) * rs * g1.y + b1.y,
        (v1.z - mu) * rs * g1.z + b1.z, (v1.w - mu) * rs * g1.w + b1.w };

    union { __half h[8]; uint4 u; } H;
    #pragma unroll
    for (int i = 0; i < 8; i++) H.h[i] = __float2half(xn[i]);
    *reinterpret_cast<uint4*>(&g_A[(size_t)row * D + t * 8]) = H.u;
}

// ------------------------- Stage 2: W transpose -> fp16 -------------
__global__ __launch_bounds__(256)
void wsplit_kernel(const float* __restrict__ W, int K, int N) {
    __shared__ float tile[32][33];
    const int k0 = blockIdx.y * 32, n0 = blockIdx.x * 32;
    const int tx = threadIdx.x, ty = threadIdx.y;  // 32 x 8
    #pragma unroll
    for (int r = 0; r < 32; r += 8)
        tile[ty + r][tx] = W[(size_t)(k0 + ty + r) * N + n0 + tx];
    __syncthreads();
    #pragma unroll
    for (int r = 0; r < 32; r += 8) {
        const int n = n0 + ty + r, k = k0 + tx;
        g_B[(size_t)n * K + k] = __float2half(tile[tx][ty + r]);
    }
}

// ------------------------- Stage 3: GEMM ----------------------------
static constexpr int BM = 128, BN = 256, BK = 64;
static constexpr int THREADS = 512;
// per-stage (128B rows): A [0,16K) B [16K,48K)
static constexpr int B_OFF     = 16384;
static constexpr int STAGE_BYTES = 49152;
static constexpr int SMEM_TOTAL  = 1024 + 2 * STAGE_BYTES;  // 99328

__global__ __launch_bounds__(THREADS, 1)
void ffn_mma_kernel(const float* __restrict__ x,
                    const float* __restrict__ bias,
                    float* __restrict__ out,
                    int K, int H) {
    extern __shared__ __align__(1024) uint8_t dynsmem[];
    uint32_t sb = smem_u32(dynsmem);
    sb = (sb + 1023) & ~1023u;

    const int t    = threadIdx.x;
    const int lane = t & 31;
    const int wid  = t >> 5;
    const int g    = lane >> 2;
    const int tg   = lane & 3;
    const int m0   = blockIdx.y * BM;
    const int n0   = blockIdx.x * BN;
    const int wm   = (wid >> 3) * 64;   // 0 or 64
    const int wn   = (wid & 7)  * 32;   // 0..224

    // ---- cp.async: 128B rows, 8 x 16B chunks/row ----
    const int ldrow = t >> 3;            // 0..63
    const int ldc   = t & 7;             // chunk within row
    const size_t aoff = (size_t)(m0 + ldrow) * K + ldc * 8;
    const size_t boff = (size_t)(n0 + ldrow) * K + ldc * 8;
    const __half* pA = g_A + aoff;
    const __half* pB = g_B + boff;
    const size_t rstep = (size_t)64 * K;   // +64 rows

    const uint32_t dstA = sb + swz((uint32_t)(ldrow * 128 + ldc * 16));
    const uint32_t dstB = sb + B_OFF + swz((uint32_t)(ldrow * 128 + ldc * 16));

    // ---- ldmatrix base addresses (stage 0, ks=0) ----
    const int matid = lane >> 3, r8 = lane & 7;
    uint32_t aAdr[4], bAdr[2];
    #pragma unroll
    for (int mt = 0; mt < 4; mt++) {
        const uint32_t m = wm + mt * 16 + (matid & 1) * 8 + r8;
        aAdr[mt] = sb + swz(m * 128 + (matid >> 1) * 16);
    }
    #pragma unroll
    for (int p = 0; p < 2; p++) {
        const uint32_t n = wn + p * 16 + (matid >> 1) * 8 + r8;
        bAdr[p] = sb + B_OFF + swz(n * 128 + (matid & 1) * 16);
    }

    float acc[4][4][4];
    #pragma unroll
    for (int mt = 0; mt < 4; mt++)
        #pragma unroll
        for (int nt = 0; nt < 4; nt++)
            #pragma unroll
            for (int r = 0; r < 4; r++) acc[mt][nt][r] = 0.f;

    const int NT = K / BK;   // 32

    auto load_stage = [&](int kt, int buf) {
        const uint32_t so = buf * STAGE_BYTES;
        const int kc = kt * BK;
        const __half* a = pA + kc;
        const __half* b = pB + kc;
        cp16(dstA + so,        a);
        cp16(dstA + so + 8192, a + rstep);
        #pragma unroll
        for (int i = 0; i < 4; i++)
            cp16(dstB + so + i * 8192, b + i * rstep);
    };

    load_stage(0, 0);
    asm volatile("cp.async.commit_group;" ::: "memory");

    for (int kt = 0; kt < NT; kt++) {
        const int cur = kt & 1;

        if (kt + 1 < NT) load_stage(kt + 1, cur ^ 1);
        asm volatile("cp.async.commit_group;" ::: "memory");

        asm volatile("cp.async.wait_group 1;" ::: "memory");
        __syncthreads();

        const uint32_t so = cur * STAGE_BYTES;

        #pragma unroll
        for (int ks = 0; ks < 4; ks++) {
            const uint32_t kx = ks * 32;   // XOR step, swizzle-transparent
            uint32_t bh[8];
            #pragma unroll
            for (int p = 0; p < 2; p++)
                ldsm4(&bh[p * 4], (bAdr[p] + so) ^ kx);
            uint32_t ah[4][4];
            #pragma unroll
            for (int mt = 0; mt < 4; mt++)
                ldsm4(ah[mt], (aAdr[mt] + so) ^ kx);
            #pragma unroll
            for (int mt = 0; mt < 4; mt++)
                #pragma unroll
                for (int nt = 0; nt < 4; nt++)
                    mma16816(acc[mt][nt], ah[mt], &bh[nt * 2]);
        }
        __syncthreads();
    }

    // ---- epilogue: bias + exact GELU + residual ----
    #pragma unroll
    for (int mt = 0; mt < 4; mt++) {
        #pragma unroll
        for (int half = 0; half < 2; half++) {
            const int m = m0 + wm + mt * 16 + g + half * 8;
            const float* xr = x + (size_t)m * H;
            float* orow = out + (size_t)m * H;
            #pragma unroll
            for (int nt = 0; nt < 4; nt++) {
                const int n = n0 + wn + nt * 8 + tg * 2;
                float c0 = acc[mt][nt][half * 2 + 0];
                float c1 = acc[mt][nt][half * 2 + 1];
                const float2 bb = *reinterpret_cast<const float2*>(bias + n);
                float h0 = c0 + bb.x, h1 = c1 + bb.y;
                h0 = 0.5f * h0 * (1.0f + erff(h0 * 0.70710678118654752f));
                h1 = 0.5f * h1 * (1.0f + erff(h1 * 0.70710678118654752f));
                const float2 xv = *reinterpret_cast<const float2*>(xr + n);
                float2 o;
                o.x = h0 + xv.x;
                o.y = h1 + xv.y;
                *reinterpret_cast<float2*>(orow + n) = o;
            }
        }
    }
}

// ------------------------- host side ---------------------------------
extern "C" void kernel_launch(void* const* d_in, const int* in_sizes, int n_in,
                              void* d_out, int out_size) {
    const float* x     = (const float*)d_in[0];
    const float* gamma = (const float*)d_in[1];
    const float* beta  = (const float*)d_in[2];
    const float* W     = (const float*)d_in[3];
    const float* bias  = (const float*)d_in[4];
    float* out = (float*)d_out;

    const int D = in_sizes[1];
    const int H = in_sizes[4];
    const int M = in_sizes[0] / D;

    ln_split_kernel<<<M, 256>>>(x, gamma, beta, D);

    dim3 wgrid(H / 32, D / 32);
    wsplit_kernel<<<wgrid, dim3(32, 8)>>>(W, D, H);

    cudaFuncSetAttribute(ffn_mma_kernel,
                         cudaFuncAttributeMaxDynamicSharedMemorySize, SMEM_TOTAL);
    dim3 ggrid(H / BN, M / BM);
    ffn_mma_kernel<<<ggrid, THREADS, SMEM_TOTAL>>>(x, bias, out, D, H);
}

// round 10
// speedup vs baseline: 7.2350x; 1.1291x over previous
#include <cuda_runtime.h>
#include <cuda_fp16.h>
#include <cstdint>

// =====================================================================
// Fused LayerNorm -> Linear -> exact GELU -> residual
//   x [M=32768, D=2048] fp32, W [D, H=2048] fp32, out [M, H] fp32
// R10: occ=2 GEMM (BM=128, BN=128, 256 thr, 3-stage x 32KB pipeline)
//   so epilogue/barrier bubbles of one CTA overlap the other's MMAs.
//   D = A_fp16 * B_fp16 (fp32 accumulate), rel_err ~1.7e-4.
// =====================================================================

#define LN_EPS 1e-5f
static constexpr int MROWS = 32768;
static constexpr int DDIM  = 2048;

__device__ __align__(1024) __half g_A[(size_t)MROWS * DDIM];   // LN(x) fp16
__device__ __align__(1024) __half g_B[(size_t)DDIM * DDIM];    // W^T fp16 [N,K]

// ------------------------- helpers ----------------------------------
__device__ __forceinline__ uint32_t smem_u32(const void* p) {
    uint32_t a;
    asm("{ .reg .u64 t; cvta.to.shared.u64 t, %1; cvt.u32.u64 %0, t; }"
        : "=r"(a) : "l"(p));
    return a;
}
__device__ __forceinline__ uint32_t swz(uint32_t off) {   // SW128: bits[6:4] ^= bits[9:7]
    return off ^ ((off >> 3) & 0x70u);
}
__device__ __forceinline__ void cp16(uint32_t dst, const void* src) {
    asm volatile("cp.async.cg.shared.global [%0], [%1], 16;" :: "r"(dst), "l"(src));
}
__device__ __forceinline__ void ldsm4(uint32_t* r, uint32_t a) {
    asm volatile("ldmatrix.sync.aligned.m8n8.x4.shared.b16 {%0,%1,%2,%3}, [%4];"
        : "=r"(r[0]), "=r"(r[1]), "=r"(r[2]), "=r"(r[3]) : "r"(a));
}
__device__ __forceinline__ void mma16816(float* c, const uint32_t* a, const uint32_t* b) {
    asm volatile(
        "mma.sync.aligned.m16n8k16.row.col.f32.f16.f16.f32 "
        "{%0,%1,%2,%3}, {%4,%5,%6,%7}, {%8,%9}, {%0,%1,%2,%3};"
        : "+f"(c[0]), "+f"(c[1]), "+f"(c[2]), "+f"(c[3])
        : "r"(a[0]), "r"(a[1]), "r"(a[2]), "r"(a[3]), "r"(b[0]), "r"(b[1]));
}

// ------------------------- Stage 1: LN -> fp16 ----------------------
__global__ __launch_bounds__(256)
void ln_split_kernel(const float* __restrict__ x,
                     const float* __restrict__ gamma,
                     const float* __restrict__ beta, int D) {
    const int row = blockIdx.x;
    const int t = threadIdx.x;
    const float* xr = x + (size_t)row * D;

    float4 v0 = *reinterpret_cast<const float4*>(xr + t * 8);
    float4 v1 = *reinterpret_cast<const float4*>(xr + t * 8 + 4);

    float s  = v0.x + v0.y + v0.z + v0.w + v1.x + v1.y + v1.z + v1.w;
    float s2 = v0.x*v0.x + v0.y*v0.y + v0.z*v0.z + v0.w*v0.w
             + v1.x*v1.x + v1.y*v1.y + v1.z*v1.z + v1.w*v1.w;
    #pragma unroll
    for (int o = 16; o > 0; o >>= 1) {
        s  += __shfl_down_sync(0xFFFFFFFFu, s, o);
        s2 += __shfl_down_sync(0xFFFFFFFFu, s2, o);
    }
    __shared__ float ps[8], ps2[8], s_mu, s_rs;
    const int wid = t >> 5, lane = t & 31;
    if (lane == 0) { ps[wid] = s; ps2[wid] = s2; }
    __syncthreads();
    if (t == 0) {
        float S = 0.f, S2 = 0.f;
        #pragma unroll
        for (int i = 0; i < 8; i++) { S += ps[i]; S2 += ps2[i]; }
        float m = S / (float)D;
        s_mu = m;
        s_rs = rsqrtf(S2 / (float)D - m * m + LN_EPS);
    }
    __syncthreads();
    const float mu = s_mu, rs = s_rs;

    float4 g0 = *reinterpret_cast<const float4*>(gamma + t * 8);
    float4 g1 = *reinterpret_cast<const float4*>(gamma + t * 8 + 4);
    float4 b0 = *reinterpret_cast<const float4*>(beta  + t * 8);
    float4 b1 = *reinterpret_cast<const float4*>(beta  + t * 8 + 4);

    float xn[8] = {
        (v0.x - mu) * rs * g0.x + b0.x, (v0.y - mu) * rs * g0.y + b0.y,
        (v0.z - mu) * rs * g0.z + b0.z, (v0.w - mu) * rs * g0.w + b0.w,
        (v1.x - mu) * rs * g1.x + b1.x, (v1.y - mu) * rs * g1.y + b1.y,
        (v1.z - mu) * rs * g1.z + b1.z, (v1.w - mu) * rs * g1.w + b1.w };

    union { __half h[8]; uint4 u; } H;
    #pragma unroll
    for (int i = 0; i < 8; i++) H.h[i] = __float2half(xn[i]);
    *reinterpret_cast<uint4*>(&g_A[(size_t)row * D + t * 8]) = H.u;
}

// ------------------------- Stage 2: W transpose -> fp16 -------------
__global__ __launch_bounds__(256)
void wsplit_kernel(const float* __restrict__ W, int K, int N) {
    __shared__ float tile[32][33];
    const int k0 = blockIdx.y * 32, n0 = blockIdx.x * 32;
    const int tx = threadIdx.x, ty = threadIdx.y;  // 32 x 8
    #pragma unroll
    for (int r = 0; r < 32; r += 8)
        tile[ty + r][tx] = W[(size_t)(k0 + ty + r) * N + n0 + tx];
    __syncthreads();
    #pragma unroll
    for (int r = 0; r < 32; r += 8) {
        const int n = n0 + ty + r, k = k0 + tx;
        g_B[(size_t)n * K + k] = __float2half(tile[tx][ty + r]);
    }
}

// ------------------------- Stage 3: GEMM ----------------------------
static constexpr int BM = 128, BN = 128, BK = 64;
static constexpr int THREADS = 256;
static constexpr int STAGES = 3;
// per-stage (128B rows): A [0,16K) B [16K,32K)
static constexpr int B_OFF       = 16384;
static constexpr int STAGE_BYTES = 32768;
static constexpr int SMEM_TOTAL  = 1024 + STAGES * STAGE_BYTES;  // 99328/CTA

__global__ __launch_bounds__(THREADS, 2)
void ffn_mma_kernel(const float* __restrict__ x,
                    const float* __restrict__ bias,
                    float* __restrict__ out,
                    int K, int H) {
    extern __shared__ __align__(1024) uint8_t dynsmem[];
    uint32_t sb = smem_u32(dynsmem);
    sb = (sb + 1023) & ~1023u;

    const int t    = threadIdx.x;
    const int lane = t & 31;
    const int wid  = t >> 5;
    const int g    = lane >> 2;
    const int tg   = lane & 3;
    const int m0   = blockIdx.y * BM;
    const int n0   = blockIdx.x * BN;
    const int wm   = (wid >> 2) * 64;   // 0 or 64
    const int wn   = (wid & 3)  * 32;   // 0..96

    // ---- cp.async: 128B rows, 8 x 16B chunks/row; 4 A + 4 B per thread
    const int ldrow = t >> 3;            // 0..31
    const int ldc   = t & 7;             // chunk within row
    const size_t aoff = (size_t)(m0 + ldrow) * K + ldc * 8;
    const size_t boff = (size_t)(n0 + ldrow) * K + ldc * 8;
    const __half* pA = g_A + aoff;
    const __half* pB = g_B + boff;
    const size_t rstep = (size_t)32 * K;   // +32 rows per chunk-block

    const uint32_t dstA = sb + swz((uint32_t)(ldrow * 128 + ldc * 16));
    const uint32_t dstB = sb + B_OFF + swz((uint32_t)(ldrow * 128 + ldc * 16));

    // ---- ldmatrix base addresses (stage 0, ks=0) ----
    const int matid = lane >> 3, r8 = lane & 7;
    uint32_t aAdr[4], bAdr[2];
    #pragma unroll
    for (int mt = 0; mt < 4; mt++) {
        const uint32_t m = wm + mt * 16 + (matid & 1) * 8 + r8;
        aAdr[mt] = sb + swz(m * 128 + (matid >> 1) * 16);
    }
    #pragma unroll
    for (int p = 0; p < 2; p++) {
        const uint32_t n = wn + p * 16 + (matid >> 1) * 8 + r8;
        bAdr[p] = sb + B_OFF + swz(n * 128 + (matid & 1) * 16);
    }

    float acc[4][4][4];
    #pragma unroll
    for (int mt = 0; mt < 4; mt++)
        #pragma unroll
        for (int nt = 0; nt < 4; nt++)
            #pragma unroll
            for (int r = 0; r < 4; r++) acc[mt][nt][r] = 0.f;

    const int NT = K / BK;   // 32

    auto load_stage = [&](int kt, uint32_t so) {
        const int kc = kt * BK;
        const __half* a = pA + kc;
        const __half* b = pB + kc;
        #pragma unroll
        for (int i = 0; i < 4; i++) {
            cp16(dstA + so + i * 4096, a + i * rstep);
            cp16(dstB + so + i * 4096, b + i * rstep);
        }
    };

    // ---- prologue: stages 0, 1 ----
    load_stage(0, 0);
    asm volatile("cp.async.commit_group;" ::: "memory");
    load_stage(1, STAGE_BYTES);
    asm volatile("cp.async.commit_group;" ::: "memory");

    // ring counters: cur = kt%3, nxt2 = (kt+2)%3
    int cur = 0, nxt2 = 2;

    for (int kt = 0; kt < NT; kt++) {
        asm volatile("cp.async.wait_group 1;" ::: "memory");  // stage cur ready
        __syncthreads();  // everyone done reading the buffer we now overwrite

        if (kt + 2 < NT) load_stage(kt + 2, nxt2 * STAGE_BYTES);
        asm volatile("cp.async.commit_group;" ::: "memory");

        const uint32_t so = cur * STAGE_BYTES;

        #pragma unroll
        for (int ks = 0; ks < 4; ks++) {
            const uint32_t kx = ks * 32;   // XOR step, swizzle-transparent
            uint32_t bh[8];
            #pragma unroll
            for (int p = 0; p < 2; p++)
                ldsm4(&bh[p * 4], (bAdr[p] + so) ^ kx);
            uint32_t ah[4][4];
            #pragma unroll
            for (int mt = 0; mt < 4; mt++)
                ldsm4(ah[mt], (aAdr[mt] + so) ^ kx);
            #pragma unroll
            for (int mt = 0; mt < 4; mt++)
                #pragma unroll
                for (int nt = 0; nt < 4; nt++)
                    mma16816(acc[mt][nt], ah[mt], &bh[nt * 2]);
        }

        cur  = (cur  == 2) ? 0 : cur  + 1;
        nxt2 = (nxt2 == 2) ? 0 : nxt2 + 1;
    }

    // ---- epilogue: bias + exact GELU + residual ----
    #pragma unroll
    for (int mt = 0; mt < 4; mt++) {
        #pragma unroll
        for (int half = 0; half < 2; half++) {
            const int m = m0 + wm + mt * 16 + g + half * 8;
            const float* xr = x + (size_t)m * H;
            float* orow = out + (size_t)m * H;
            #pragma unroll
            for (int nt = 0; nt < 4; nt++) {
                const int n = n0 + wn + nt * 8 + tg * 2;
                float c0 = acc[mt][nt][half * 2 + 0];
                float c1 = acc[mt][nt][half * 2 + 1];
                const float2 bb = *reinterpret_cast<const float2*>(bias + n);
                float h0 = c0 + bb.x, h1 = c1 + bb.y;
                h0 = 0.5f * h0 * (1.0f + erff(h0 * 0.70710678118654752f));
                h1 = 0.5f * h1 * (1.0f + erff(h1 * 0.70710678118654752f));
                const float2 xv = *reinterpret_cast<const float2*>(xr + n);
                float2 o;
                o.x = h0 + xv.x;
                o.y = h1 + xv.y;
                *reinterpret_cast<float2*>(orow + n) = o;
            }
        }
    }
}

// ------------------------- host side ---------------------------------
extern "C" void kernel_launch(void* const* d_in, const int* in_sizes, int n_in,
                              void* d_out, int out_size) {
    const float* x     = (const float*)d_in[0];
    const float* gamma = (const float*)d_in[1];
    const float* beta  = (const float*)d_in[2];
    const float* W     = (const float*)d_in[3];
    const float* bias  = (const float*)d_in[4];
    float* out = (float*)d_out;

    const int D = in_sizes[1];
    const int H = in_sizes[4];
    const int M = in_sizes[0] / D;

    ln_split_kernel<<<M, 256>>>(x, gamma, beta, D);

    dim3 wgrid(H / 32, D / 32);
    wsplit_kernel<<<wgrid, dim3(32, 8)>>>(W, D, H);

    cudaFuncSetAttribute(ffn_mma_kernel,
                         cudaFuncAttributeMaxDynamicSharedMemorySize, SMEM_TOTAL);
    dim3 ggrid(H / BN, M / BM);
    ffn_mma_kernel<<<ggrid, THREADS, SMEM_TOTAL>>>(x, bias, out, D, H);
}

// round 11
// speedup vs baseline: 7.3806x; 1.0201x over previous
#include <cuda_runtime.h>
#include <cuda_fp16.h>
#include <cstdint>

// =====================================================================
// Fused LayerNorm -> Linear -> exact GELU -> residual
//   x [M=32768, D=2048] fp32, W [D, H=2048] fp32, out [M, H] fp32
// R11: warp-per-row LN (no block barriers, MLP=16) feeding the R10
//      occ=2 fp16 mma.sync GEMM (BM=BN=128, 3-stage cp.async).
//   D = A_fp16 * B_fp16 (fp32 accumulate), rel_err ~1.7e-4.
// =====================================================================

#define LN_EPS 1e-5f
static constexpr int MROWS = 32768;
static constexpr int DDIM  = 2048;

__device__ __align__(1024) __half g_A[(size_t)MROWS * DDIM];   // LN(x) fp16
__device__ __align__(1024) __half g_B[(size_t)DDIM * DDIM];    // W^T fp16 [N,K]

// ------------------------- helpers ----------------------------------
__device__ __forceinline__ uint32_t smem_u32(const void* p) {
    uint32_t a;
    asm("{ .reg .u64 t; cvta.to.shared.u64 t, %1; cvt.u32.u64 %0, t; }"
        : "=r"(a) : "l"(p));
    return a;
}
__device__ __forceinline__ uint32_t swz(uint32_t off) {   // SW128: bits[6:4] ^= bits[9:7]
    return off ^ ((off >> 3) & 0x70u);
}
__device__ __forceinline__ void cp16(uint32_t dst, const void* src) {
    asm volatile("cp.async.cg.shared.global [%0], [%1], 16;" :: "r"(dst), "l"(src));
}
__device__ __forceinline__ void ldsm4(uint32_t* r, uint32_t a) {
    asm volatile("ldmatrix.sync.aligned.m8n8.x4.shared.b16 {%0,%1,%2,%3}, [%4];"
        : "=r"(r[0]), "=r"(r[1]), "=r"(r[2]), "=r"(r[3]) : "r"(a));
}
__device__ __forceinline__ void mma16816(float* c, const uint32_t* a, const uint32_t* b) {
    asm volatile(
        "mma.sync.aligned.m16n8k16.row.col.f32.f16.f16.f32 "
        "{%0,%1,%2,%3}, {%4,%5,%6,%7}, {%8,%9}, {%0,%1,%2,%3};"
        : "+f"(c[0]), "+f"(c[1]), "+f"(c[2]), "+f"(c[3])
        : "r"(a[0]), "r"(a[1]), "r"(a[2]), "r"(a[3]), "r"(b[0]), "r"(b[1]));
}

// ------------------------- Stage 1: warp-per-row LN -> fp16 ---------
// 256 threads = 8 warps = 8 rows per block; each lane owns 64 elements
// (16 x float4, front-batched -> MLP=16). Warp-local bfly reduction.
__global__ __launch_bounds__(256)
void ln_kernel(const float* __restrict__ x,
               const float* __restrict__ gamma,
               const float* __restrict__ beta, int D) {
    const int wid  = threadIdx.x >> 5;
    const int lane = threadIdx.x & 31;
    const int row  = blockIdx.x * 8 + wid;
    const float* xr = x + (size_t)row * D;

    float4 v[16];
    #pragma unroll
    for (int i = 0; i < 16; i++)
        v[i] = *reinterpret_cast<const float4*>(xr + (i * 32 + lane) * 4);

    float s = 0.f, s2 = 0.f;
    #pragma unroll
    for (int i = 0; i < 16; i++) {
        s  += v[i].x + v[i].y + v[i].z + v[i].w;
        s2 += v[i].x * v[i].x + v[i].y * v[i].y
            + v[i].z * v[i].z + v[i].w * v[i].w;
    }
    #pragma unroll
    for (int o = 16; o > 0; o >>= 1) {
        s  += __shfl_xor_sync(0xFFFFFFFFu, s, o);
        s2 += __shfl_xor_sync(0xFFFFFFFFu, s2, o);
    }
    const float mu = s / (float)D;
    const float rs = rsqrtf(s2 / (float)D - mu * mu + LN_EPS);

    __half* arow = g_A + (size_t)row * D;
    #pragma unroll
    for (int i = 0; i < 16; i++) {
        const int c = (i * 32 + lane) * 4;
        const float4 g4 = *reinterpret_cast<const float4*>(gamma + c);
        const float4 b4 = *reinterpret_cast<const float4*>(beta  + c);
        union { __half h[4]; uint2 u; } o;
        o.h[0] = __float2half((v[i].x - mu) * rs * g4.x + b4.x);
        o.h[1] = __float2half((v[i].y - mu) * rs * g4.y + b4.y);
        o.h[2] = __float2half((v[i].z - mu) * rs * g4.z + b4.z);
        o.h[3] = __float2half((v[i].w - mu) * rs * g4.w + b4.w);
        *reinterpret_cast<uint2*>(arow + c) = o.u;
    }
}

// ------------------------- Stage 2: W transpose -> fp16 -------------
__global__ __launch_bounds__(256)
void wsplit_kernel(const float* __restrict__ W, int K, int N) {
    __shared__ float tile[32][33];
    const int k0 = blockIdx.y * 32, n0 = blockIdx.x * 32;
    const int tx = threadIdx.x, ty = threadIdx.y;  // 32 x 8
    #pragma unroll
    for (int r = 0; r < 32; r += 8)
        tile[ty + r][tx] = W[(size_t)(k0 + ty + r) * N + n0 + tx];
    __syncthreads();
    #pragma unroll
    for (int r = 0; r < 32; r += 8) {
        const int n = n0 + ty + r, k = k0 + tx;
        g_B[(size_t)n * K + k] = __float2half(tile[tx][ty + r]);
    }
}

// ------------------------- Stage 3: GEMM ----------------------------
static constexpr int BM = 128, BN = 128, BK = 64;
static constexpr int THREADS = 256;
static constexpr int STAGES = 3;
// per-stage (128B rows): A [0,16K) B [16K,32K)
static constexpr int B_OFF       = 16384;
static constexpr int STAGE_BYTES = 32768;
static constexpr int SMEM_TOTAL  = 1024 + STAGES * STAGE_BYTES;  // 99328/CTA

__global__ __launch_bounds__(THREADS, 2)
void ffn_mma_kernel(const float* __restrict__ x,
                    const float* __restrict__ bias,
                    float* __restrict__ out,
                    int K, int H) {
    extern __shared__ __align__(1024) uint8_t dynsmem[];
    uint32_t sb = smem_u32(dynsmem);
    sb = (sb + 1023) & ~1023u;

    const int t    = threadIdx.x;
    const int lane = t & 31;
    const int wid  = t >> 5;
    const int g    = lane >> 2;
    const int tg   = lane & 3;
    const int m0   = blockIdx.y * BM;
    const int n0   = blockIdx.x * BN;
    const int wm   = (wid >> 2) * 64;   // 0 or 64
    const int wn   = (wid & 3)  * 32;   // 0..96

    // ---- cp.async: 128B rows, 8 x 16B chunks/row; 4 A + 4 B per thread
    const int ldrow = t >> 3;            // 0..31
    const int ldc   = t & 7;             // chunk within row
    const size_t aoff = (size_t)(m0 + ldrow) * K + ldc * 8;
    const size_t boff = (size_t)(n0 + ldrow) * K + ldc * 8;
    const __half* pA = g_A + aoff;
    const __half* pB = g_B + boff;
    const size_t rstep = (size_t)32 * K;   // +32 rows per chunk-block

    const uint32_t dstA = sb + swz((uint32_t)(ldrow * 128 + ldc * 16));
    const uint32_t dstB = sb + B_OFF + swz((uint32_t)(ldrow * 128 + ldc * 16));

    // ---- ldmatrix base addresses (stage 0, ks=0) ----
    const int matid = lane >> 3, r8 = lane & 7;
    uint32_t aAdr[4], bAdr[2];
    #pragma unroll
    for (int mt = 0; mt < 4; mt++) {
        const uint32_t m = wm + mt * 16 + (matid & 1) * 8 + r8;
        aAdr[mt] = sb + swz(m * 128 + (matid >> 1) * 16);
    }
    #pragma unroll
    for (int p = 0; p < 2; p++) {
        const uint32_t n = wn + p * 16 + (matid >> 1) * 8 + r8;
        bAdr[p] = sb + B_OFF + swz(n * 128 + (matid & 1) * 16);
    }

    float acc[4][4][4];
    #pragma unroll
    for (int mt = 0; mt < 4; mt++)
        #pragma unroll
        for (int nt = 0; nt < 4; nt++)
            #pragma unroll
            for (int r = 0; r < 4; r++) acc[mt][nt][r] = 0.f;

    const int NT = K / BK;   // 32

    auto load_stage = [&](int kt, uint32_t so) {
        const int kc = kt * BK;
        const __half* a = pA + kc;
        const __half* b = pB + kc;
        #pragma unroll
        for (int i = 0; i < 4; i++) {
            cp16(dstA + so + i * 4096, a + i * rstep);
            cp16(dstB + so + i * 4096, b + i * rstep);
        }
    };

    // ---- prologue: stages 0, 1 ----
    load_stage(0, 0);
    asm volatile("cp.async.commit_group;" ::: "memory");
    load_stage(1, STAGE_BYTES);
    asm volatile("cp.async.commit_group;" ::: "memory");

    int cur = 0, nxt2 = 2;

    for (int kt = 0; kt < NT; kt++) {
        asm volatile("cp.async.wait_group 1;" ::: "memory");  // stage cur ready
        __syncthreads();  // all reads of the buffer we now overwrite are done

        if (kt + 2 < NT) load_stage(kt + 2, nxt2 * STAGE_BYTES);
        asm volatile("cp.async.commit_group;" ::: "memory");

        const uint32_t so = cur * STAGE_BYTES;

        #pragma unroll
        for (int ks = 0; ks < 4; ks++) {
            const uint32_t kx = ks * 32;   // XOR step, swizzle-transparent
            uint32_t bh[8];
            #pragma unroll
            for (int p = 0; p < 2; p++)
                ldsm4(&bh[p * 4], (bAdr[p] + so) ^ kx);
            uint32_t ah[4][4];
            #pragma unroll
            for (int mt = 0; mt < 4; mt++)
                ldsm4(ah[mt], (aAdr[mt] + so) ^ kx);
            #pragma unroll
            for (int mt = 0; mt < 4; mt++)
                #pragma unroll
                for (int nt = 0; nt < 4; nt++)
                    mma16816(acc[mt][nt], ah[mt], &bh[nt * 2]);
        }

        cur  = (cur  == 2) ? 0 : cur  + 1;
        nxt2 = (nxt2 == 2) ? 0 : nxt2 + 1;
    }

    // ---- epilogue: bias + exact GELU + residual ----
    #pragma unroll
    for (int mt = 0; mt < 4; mt++) {
        #pragma unroll
        for (int half = 0; half < 2; half++) {
            const int m = m0 + wm + mt * 16 + g + half * 8;
            const float* xr = x + (size_t)m * H;
            float* orow = out + (size_t)m * H;
            #pragma unroll
            for (int nt = 0; nt < 4; nt++) {
                const int n = n0 + wn + nt * 8 + tg * 2;
                float c0 = acc[mt][nt][half * 2 + 0];
                float c1 = acc[mt][nt][half * 2 + 1];
                const float2 bb = *reinterpret_cast<const float2*>(bias + n);
                float h0 = c0 + bb.x, h1 = c1 + bb.y;
                h0 = 0.5f * h0 * (1.0f + erff(h0 * 0.70710678118654752f));
                h1 = 0.5f * h1 * (1.0f + erff(h1 * 0.70710678118654752f));
                const float2 xv = *reinterpret_cast<const float2*>(xr + n);
                float2 o;
                o.x = h0 + xv.x;
                o.y = h1 + xv.y;
                *reinterpret_cast<float2*>(orow + n) = o;
            }
        }
    }
}

// ------------------------- host side ---------------------------------
extern "C" void kernel_launch(void* const* d_in, const int* in_sizes, int n_in,
                              void* d_out, int out_size) {
    const float* x     = (const float*)d_in[0];
    const float* gamma = (const float*)d_in[1];
    const float* beta  = (const float*)d_in[2];
    const float* W     = (const float*)d_in[3];
    const float* bias  = (const float*)d_in[4];
    float* out = (float*)d_out;

    const int D = in_sizes[1];
    const int H = in_sizes[4];
    const int M = in_sizes[0] / D;

    ln_kernel<<<M / 8, 256>>>(x, gamma, beta, D);

    dim3 wgrid(H / 32, D / 32);
    wsplit_kernel<<<wgrid, dim3(32, 8)>>>(W, D, H);

    cudaFuncSetAttribute(ffn_mma_kernel,
                         cudaFuncAttributeMaxDynamicSharedMemorySize, SMEM_TOTAL);
    dim3 ggrid(H / BN, M / BM);
    ffn_mma_kernel<<<ggrid, THREADS, SMEM_TOTAL>>>(x, bias, out, D, H);
}